// round 2
// baseline (speedup 1.0000x reference)
#include <cuda_runtime.h>
#include <math.h>

// ---------------- scratch (device globals; no allocation) ----------------
__device__ float g_L [2u*4096u*1024u];   // local (sliding window) result, tri-weighted then normalized
__device__ float g_G [2u*4096u*1024u];   // global attention result
__device__ float g_BC[2u*4096u*1024u];   // broadcast diffusion result
__device__ float g_M [2u*4096u*1024u];   // mixed
__device__ float g_COMP[2u*64u*1024u];   // conv output (first 64 tokens), bias included

// =====================================================================
// 1) broadcast diffusion: 12 roll steps fully in shared memory
//    block = (b, 4 consecutive d), 512 threads, smem = 2 x 4096 x 4 floats
// =====================================================================
__global__ void bc_kernel(const float* __restrict__ x, float* __restrict__ bc) {
    extern __shared__ float sm[];
    float* bufA = sm;            // 16384 floats
    float* bufB = sm + 16384;
    const int tid = threadIdx.x;         // 512
    const int b   = blockIdx.y;
    const int d0  = blockIdx.x << 2;
    const float* src = x + (size_t)b * 4194304u + d0;

    for (int s = tid; s < 4096; s += 512)
        *(float4*)&bufA[s << 2] = *(const float4*)(src + (size_t)s * 1024u);
    __syncthreads();

    float acc[32];
#pragma unroll
    for (int e = 0; e < 32; ++e) acc[e] = 0.f;

    float* cur = bufA; float* nxt = bufB;
    for (int st = 1; st < 4096; st <<= 1) {
#pragma unroll
        for (int q = 0; q < 8; ++q) {
            int s   = tid + (q << 9);
            int sc  = s << 2;
            int sm1 = ((s - st) & 4095) << 2;
            int sp1 = ((s + st) & 4095) << 2;
#pragma unroll
            for (int j = 0; j < 4; ++j) {
                float v = cur[sc + j] + 0.5f * (cur[sm1 + j] + cur[sp1 + j]);
                nxt[sc + j] = v;
                acc[(q << 2) + j] += v;
            }
        }
        __syncthreads();
        float* t = cur; cur = nxt; nxt = t;
    }
    const float inv = 1.0f / 13.0f;   // log2(4096)+1
    float* dst = bc + (size_t)b * 4194304u + d0;
#pragma unroll
    for (int q = 0; q < 8; ++q) {
        int s = tid + (q << 9);
        float4 o = make_float4(acc[q*4]*inv, acc[q*4+1]*inv, acc[q*4+2]*inv, acc[q*4+3]*inv);
        *(float4*)(dst + (size_t)s * 1024u) = o;
    }
}

// =====================================================================
// 2) conv1d(k=4, stride=4), only first 64 output tokens needed.
//    GEMM: (m = b*64+t : 128 rows) x (o : 1024) over K = 4096 (= d*4+k)
//    grid 64 blocks (o-tiles of 16), 256 threads, micro 4m x 2o.
// =====================================================================
__global__ void __launch_bounds__(256) conv_kernel(
        const float* __restrict__ x, const float* __restrict__ cw,
        const float* __restrict__ cb, float* __restrict__ comp) {
    __shared__ float As[32 * 129];
    __shared__ float Ws[32 * 20];
    const int tid = threadIdx.x;
    const int o0  = blockIdx.x << 4;
    const int mb  = (tid & 31) << 2;      // 4 m rows
    const int og  = (tid >> 5) << 1;      // 2 o columns

    float acc[4][2];
#pragma unroll
    for (int r = 0; r < 4; ++r) { acc[r][0] = 0.f; acc[r][1] = 0.f; }

    for (int k0 = 0; k0 < 4096; k0 += 32) {
        __syncthreads();
#pragma unroll
        for (int it = 0; it < 16; ++it) {
            int idx = tid + (it << 8);     // 0..4095
            int m   = idx & 127;
            int kc  = idx >> 7;            // 0..31
            int k   = k0 + kc;
            int bb  = m >> 6, t = m & 63;
            As[kc * 129 + m] =
                x[(size_t)bb * 4194304u + (size_t)((t << 2) + (k & 3)) * 1024u + (k >> 2)];
        }
#pragma unroll
        for (int it = 0; it < 2; ++it) {
            int idx = tid + (it << 8);     // 0..511
            int oo = idx >> 5, kc = idx & 31;
            Ws[kc * 20 + oo] = cw[(size_t)(o0 + oo) * 4096u + k0 + kc];
        }
        __syncthreads();
#pragma unroll
        for (int kc = 0; kc < 32; ++kc) {
            float a0 = As[kc*129 + mb + 0];
            float a1 = As[kc*129 + mb + 1];
            float a2 = As[kc*129 + mb + 2];
            float a3 = As[kc*129 + mb + 3];
            float w0 = Ws[kc*20 + og];
            float w1 = Ws[kc*20 + og + 1];
            acc[0][0] += a0*w0; acc[0][1] += a0*w1;
            acc[1][0] += a1*w0; acc[1][1] += a1*w1;
            acc[2][0] += a2*w0; acc[2][1] += a2*w1;
            acc[3][0] += a3*w0; acc[3][1] += a3*w1;
        }
    }
#pragma unroll
    for (int r = 0; r < 4; ++r)
#pragma unroll
        for (int c = 0; c < 2; ++c) {
            int m = mb + r, o = o0 + og + c;
            comp[(size_t)m * 1024u + o] = acc[r][c] + cb[o];
        }
}

// =====================================================================
// 3) sliding-window self-attention (flash style).
//    block = (b, h, window n, q-tile of 64). 256 threads.
//    parity 0 (even windows, disjoint, cover all S): direct store.
//    parity 1 (odd windows, disjoint): accumulate (+=).
//    Contribution is tri-weighted; normalization by den(s) is a later pass.
// =====================================================================
__global__ void __launch_bounds__(256) win_attn(
        const float* __restrict__ x, float* __restrict__ L, int parity) {
    extern __shared__ float sm[];
    float* Qs = sm;              // 64 x 129
    float* Ks = sm + 8256;       // 64 x 129
    float* Ss = sm + 16512;      // 64 x 65

    const int tid  = threadIdx.x;
    const int qt   = blockIdx.x;                 // 0..7
    const int n    = (blockIdx.y << 1) + parity; // window id
    const int b    = blockIdx.z >> 3, h = blockIdx.z & 7;
    const int base = n << 8;                     // n*256
    const int q0   = base + (qt << 6);
    const float* xb = x + (size_t)b * 4194304u + (h << 7);

#pragma unroll
    for (int it = 0; it < 8; ++it) {
        int i = tid + (it << 8);
        int r = i >> 5, c4 = (i & 31) << 2;
        float4 v = *(const float4*)(xb + (size_t)(q0 + r) * 1024u + c4);
        float* q = &Qs[r * 129 + c4];
        q[0] = v.x; q[1] = v.y; q[2] = v.z; q[3] = v.w;
    }

    const int row  = tid >> 2;
    const int dcol = (tid & 3) << 5;
    const int qb   = (tid >> 4) << 2;
    const int kb   = (tid & 15) << 2;
    const float scale = 0.08838834764831845f;   // 1/sqrt(128)

    float acc[32];
#pragma unroll
    for (int c = 0; c < 32; ++c) acc[c] = 0.f;
    float m_i = -1e30f, l_i = 0.f;

    for (int kt = 0; kt < 8; ++kt) {
        __syncthreads();
        int k0 = base + (kt << 6);
#pragma unroll
        for (int it = 0; it < 8; ++it) {
            int i = tid + (it << 8);
            int r = i >> 5, c4 = (i & 31) << 2;
            float4 v = *(const float4*)(xb + (size_t)(k0 + r) * 1024u + c4);
            float* k = &Ks[r * 129 + c4];
            k[0] = v.x; k[1] = v.y; k[2] = v.z; k[3] = v.w;
        }
        __syncthreads();

        float s4[4][4];
#pragma unroll
        for (int r = 0; r < 4; ++r)
#pragma unroll
            for (int c = 0; c < 4; ++c) s4[r][c] = 0.f;

#pragma unroll 4
        for (int d = 0; d < 128; ++d) {
            float qv[4], kv[4];
#pragma unroll
            for (int r = 0; r < 4; ++r) qv[r] = Qs[(qb + r) * 129 + d];
#pragma unroll
            for (int c = 0; c < 4; ++c) kv[c] = Ks[(kb + c) * 129 + d];
#pragma unroll
            for (int r = 0; r < 4; ++r)
#pragma unroll
                for (int c = 0; c < 4; ++c) s4[r][c] += qv[r] * kv[c];
        }
#pragma unroll
        for (int r = 0; r < 4; ++r)
#pragma unroll
            for (int c = 0; c < 4; ++c)
                Ss[(qb + r) * 65 + kb + c] = s4[r][c] * scale;
        __syncthreads();

        // online softmax (4 threads share one row)
        float mt = -1e30f;
        const int cb0 = (tid & 3) << 4;
#pragma unroll
        for (int jj = 0; jj < 16; ++jj) mt = fmaxf(mt, Ss[row * 65 + cb0 + jj]);
        mt = fmaxf(mt, __shfl_xor_sync(0xffffffffu, mt, 1));
        mt = fmaxf(mt, __shfl_xor_sync(0xffffffffu, mt, 2));
        float m_new = fmaxf(m_i, mt);
        float alpha = __expf(m_i - m_new);
#pragma unroll
        for (int c = 0; c < 32; ++c) acc[c] *= alpha;

        float lsum = 0.f;
        const float* srow = &Ss[row * 65];
#pragma unroll 4
        for (int j = 0; j < 64; ++j) {
            float p = __expf(srow[j] - m_new);
            lsum += p;
            const float* vr = &Ks[j * 129 + dcol];
#pragma unroll
            for (int c = 0; c < 32; ++c) acc[c] += p * vr[c];
        }
        l_i = l_i * alpha + lsum;
        m_i = m_new;
    }

    const float tw = (0.5f + (float)((qt << 6) + row) * (1.0f / 511.0f)) / l_i;
    float* dst = L + ((size_t)b * 4096u + q0 + row) * 1024u + (h << 7) + dcol;
    if (parity == 0) {
#pragma unroll
        for (int c = 0; c < 32; c += 4) {
            float4 o = make_float4(acc[c]*tw, acc[c+1]*tw, acc[c+2]*tw, acc[c+3]*tw);
            *(float4*)(dst + c) = o;
        }
    } else {
#pragma unroll
        for (int c = 0; c < 32; c += 4) {
            float4 o = *(float4*)(dst + c);
            o.x += acc[c]*tw; o.y += acc[c+1]*tw; o.z += acc[c+2]*tw; o.w += acc[c+3]*tw;
            *(float4*)(dst + c) = o;
        }
    }
}

// analytic overlap-add denominator
__device__ __forceinline__ float invden(int s) {
    int n1 = s >> 8, i1 = s & 255;
    float d = 0.f;
    if (n1 <= 14) d += 0.5f + (float)i1 * (1.0f / 511.0f);
    if (n1 >= 1)  d += 0.5f + (float)(i1 + 256) * (1.0f / 511.0f);
    return 1.0f / d;
}

__global__ void norm_local(float* __restrict__ L) {
    size_t i = (size_t)blockIdx.x * blockDim.x + threadIdx.x;   // float4 index
    int s = (int)((i >> 8) & 4095);
    float inv = invden(s);
    float4* p = (float4*)L;
    float4 v = p[i];
    v.x *= inv; v.y *= inv; v.z *= inv; v.w *= inv;
    p[i] = v;
}

// =====================================================================
// 4) compressed-global attention: per (b,h), KV = 128 tokens x 128d in smem.
//    block = (b, h, 32 queries). 256 threads.
// =====================================================================
__global__ void __launch_bounds__(256) gattn(
        const float* __restrict__ x, const float* __restrict__ gmem,
        const float* __restrict__ comp, float* __restrict__ G) {
    extern __shared__ float sm[];
    float* KVs = sm;                 // 128 x 129
    float* Qs  = sm + 16512;         // 32 x 129
    float* Ps  = sm + 20640;         // 32 x 129

    const int tid = threadIdx.x;
    const int s0  = blockIdx.x << 5;
    const int h   = blockIdx.y, b = blockIdx.z;

#pragma unroll
    for (int it = 0; it < 16; ++it) {
        int i = tid + (it << 8);
        int r = i >> 5, c4 = (i & 31) << 2;
        float4 v;
        if (r < 64) v = *(const float4*)(comp + (size_t)((b << 6) + r) * 1024u + (h << 7) + c4);
        else        v = *(const float4*)(gmem + (size_t)((h << 6) + (r - 64)) * 128u + c4);
        float* kv = &KVs[r * 129 + c4];
        kv[0] = v.x; kv[1] = v.y; kv[2] = v.z; kv[3] = v.w;
    }
#pragma unroll
    for (int it = 0; it < 4; ++it) {
        int i = tid + (it << 8);
        int r = i >> 5, c4 = (i & 31) << 2;
        float4 v = *(const float4*)(x + (size_t)b * 4194304u + (size_t)(s0 + r) * 1024u + (h << 7) + c4);
        float* q = &Qs[r * 129 + c4];
        q[0] = v.x; q[1] = v.y; q[2] = v.z; q[3] = v.w;
    }
    __syncthreads();

    // scores: 32q x 128t, 4x4 micro
    {
        const int qb = (tid & 7) << 2;
        const int tb = (tid >> 3) << 2;
        float s4[4][4];
#pragma unroll
        for (int r = 0; r < 4; ++r)
#pragma unroll
            for (int c = 0; c < 4; ++c) s4[r][c] = 0.f;
#pragma unroll 4
        for (int d = 0; d < 128; ++d) {
            float qv[4], kv[4];
#pragma unroll
            for (int r = 0; r < 4; ++r) qv[r] = Qs[(qb + r) * 129 + d];
#pragma unroll
            for (int c = 0; c < 4; ++c) kv[c] = KVs[(tb + c) * 129 + d];
#pragma unroll
            for (int r = 0; r < 4; ++r)
#pragma unroll
                for (int c = 0; c < 4; ++c) s4[r][c] += qv[r] * kv[c];
        }
        const float scale = 0.08838834764831845f;
#pragma unroll
        for (int r = 0; r < 4; ++r)
#pragma unroll
            for (int c = 0; c < 4; ++c)
                Ps[(qb + r) * 129 + tb + c] = s4[r][c] * scale;
    }
    __syncthreads();

    // softmax: 8 warps x 4 rows, 8 lanes per row
    {
        int lane = tid & 31, wid = tid >> 5;
        int row = (wid << 2) + (lane >> 3);
        int c0  = (lane & 7) << 4;
        float* pr = &Ps[row * 129 + c0];
        float mt = -1e30f;
        float pv[16];
#pragma unroll
        for (int jj = 0; jj < 16; ++jj) mt = fmaxf(mt, pr[jj]);
        mt = fmaxf(mt, __shfl_xor_sync(0xffffffffu, mt, 1));
        mt = fmaxf(mt, __shfl_xor_sync(0xffffffffu, mt, 2));
        mt = fmaxf(mt, __shfl_xor_sync(0xffffffffu, mt, 4));
        float ssum = 0.f;
#pragma unroll
        for (int jj = 0; jj < 16; ++jj) { pv[jj] = __expf(pr[jj] - mt); ssum += pv[jj]; }
        ssum += __shfl_xor_sync(0xffffffffu, ssum, 1);
        ssum += __shfl_xor_sync(0xffffffffu, ssum, 2);
        ssum += __shfl_xor_sync(0xffffffffu, ssum, 4);
        float invs = 1.0f / ssum;
#pragma unroll
        for (int jj = 0; jj < 16; ++jj) pr[jj] = pv[jj] * invs;
    }
    __syncthreads();

    // out: 32q x 128d
    {
        const int qg = (tid & 7) << 2;
        const int dg = (tid >> 3) << 2;
        float o4[4][4];
#pragma unroll
        for (int r = 0; r < 4; ++r)
#pragma unroll
            for (int c = 0; c < 4; ++c) o4[r][c] = 0.f;
#pragma unroll 4
        for (int t = 0; t < 128; ++t) {
            float pv[4], kv[4];
#pragma unroll
            for (int r = 0; r < 4; ++r) pv[r] = Ps[(qg + r) * 129 + t];
#pragma unroll
            for (int c = 0; c < 4; ++c) kv[c] = KVs[t * 129 + dg + c];
#pragma unroll
            for (int r = 0; r < 4; ++r)
#pragma unroll
                for (int c = 0; c < 4; ++c) o4[r][c] += pv[r] * kv[c];
        }
#pragma unroll
        for (int r = 0; r < 4; ++r) {
            float4 o = make_float4(o4[r][0], o4[r][1], o4[r][2], o4[r][3]);
            *(float4*)(G + ((size_t)b * 4096u + s0 + qg + r) * 1024u + (h << 7) + dg) = o;
        }
    }
}

// =====================================================================
// 5) mix GEMM: Z = [L/den, G] @ mix_w + mix_b; M = sig(Z)*L + (1-sig)*G + BC
//    128x128 tile, 8x8 micro, 256 threads, K = 2048
// =====================================================================
__global__ void __launch_bounds__(256) gemm_mix(
        const float* __restrict__ Lp, const float* __restrict__ Gp,
        const float* __restrict__ BCp, const float* __restrict__ W,
        const float* __restrict__ mbias, float* __restrict__ Mout) {
    __shared__ float As[16 * 132];
    __shared__ float Bs[16 * 132];
    const int tid = threadIdx.x;
    const int m0  = blockIdx.x << 7;
    const int n0  = blockIdx.y << 7;
    const int am  = tid >> 1;
    const int ak  = (tid & 1) << 3;
    const int bk  = tid >> 4;
    const int bn  = (tid & 15) << 3;
    const int ty  = tid >> 4, tx = tid & 15;

    float acc[8][8];
#pragma unroll
    for (int r = 0; r < 8; ++r)
#pragma unroll
        for (int c = 0; c < 8; ++c) acc[r][c] = 0.f;

    float4 pa0, pa1, pb0, pb1;
    auto fetch = [&](int k0) {
        int k = k0 + ak;
        const float* src = (k < 1024)
            ? (Lp + (size_t)(m0 + am) * 1024u + k)
            : (Gp + (size_t)(m0 + am) * 1024u + (k - 1024));
        pa0 = *(const float4*)src;
        pa1 = *(const float4*)(src + 4);
        const float* bsrc = W + (size_t)(k0 + bk) * 1024u + n0 + bn;
        pb0 = *(const float4*)bsrc;
        pb1 = *(const float4*)(bsrc + 4);
    };
    fetch(0);
    for (int k0 = 0; k0 < 2048; k0 += 16) {
        As[(ak+0)*132 + am] = pa0.x; As[(ak+1)*132 + am] = pa0.y;
        As[(ak+2)*132 + am] = pa0.z; As[(ak+3)*132 + am] = pa0.w;
        As[(ak+4)*132 + am] = pa1.x; As[(ak+5)*132 + am] = pa1.y;
        As[(ak+6)*132 + am] = pa1.z; As[(ak+7)*132 + am] = pa1.w;
        *(float4*)&Bs[bk*132 + bn]     = pb0;
        *(float4*)&Bs[bk*132 + bn + 4] = pb1;
        __syncthreads();
        if (k0 + 16 < 2048) fetch(k0 + 16);
#pragma unroll
        for (int kk = 0; kk < 16; ++kk) {
            float4 a0 = *(float4*)&As[kk*132 + (ty << 3)];
            float4 a1 = *(float4*)&As[kk*132 + (ty << 3) + 4];
            float4 b0 = *(float4*)&Bs[kk*132 + (tx << 3)];
            float4 b1 = *(float4*)&Bs[kk*132 + (tx << 3) + 4];
            float av[8] = {a0.x,a0.y,a0.z,a0.w,a1.x,a1.y,a1.z,a1.w};
            float bv[8] = {b0.x,b0.y,b0.z,b0.w,b1.x,b1.y,b1.z,b1.w};
#pragma unroll
            for (int r = 0; r < 8; ++r)
#pragma unroll
                for (int c = 0; c < 8; ++c) acc[r][c] += av[r] * bv[c];
        }
        __syncthreads();
    }
#pragma unroll
    for (int r = 0; r < 8; ++r) {
        int m = m0 + (ty << 3) + r;
        size_t base = (size_t)m * 1024u + n0 + (tx << 3);
#pragma unroll
        for (int c = 0; c < 8; ++c) {
            int nn = n0 + (tx << 3) + c;
            float z = acc[r][c] + mbias[nn];
            float gate = 1.0f / (1.0f + __expf(-z));
            float lv = Lp[base + c], gv = Gp[base + c], bv = BCp[base + c];
            Mout[base + c] = gate * lv + (1.0f - gate) * gv + bv;
        }
    }
}

// =====================================================================
// 6) out GEMM: OUT = M @ out_w + out_b, K = 1024
// =====================================================================
__global__ void __launch_bounds__(256) gemm_out(
        const float* __restrict__ A, const float* __restrict__ W,
        const float* __restrict__ obias, float* __restrict__ OUT) {
    __shared__ float As[16 * 132];
    __shared__ float Bs[16 * 132];
    const int tid = threadIdx.x;
    const int m0  = blockIdx.x << 7;
    const int n0  = blockIdx.y << 7;
    const int am  = tid >> 1;
    const int ak  = (tid & 1) << 3;
    const int bk  = tid >> 4;
    const int bn  = (tid & 15) << 3;
    const int ty  = tid >> 4, tx = tid & 15;

    float acc[8][8];
#pragma unroll
    for (int r = 0; r < 8; ++r)
#pragma unroll
        for (int c = 0; c < 8; ++c) acc[r][c] = 0.f;

    float4 pa0, pa1, pb0, pb1;
    auto fetch = [&](int k0) {
        const float* src = A + (size_t)(m0 + am) * 1024u + k0 + ak;
        pa0 = *(const float4*)src;
        pa1 = *(const float4*)(src + 4);
        const float* bsrc = W + (size_t)(k0 + bk) * 1024u + n0 + bn;
        pb0 = *(const float4*)bsrc;
        pb1 = *(const float4*)(bsrc + 4);
    };
    fetch(0);
    for (int k0 = 0; k0 < 1024; k0 += 16) {
        As[(ak+0)*132 + am] = pa0.x; As[(ak+1)*132 + am] = pa0.y;
        As[(ak+2)*132 + am] = pa0.z; As[(ak+3)*132 + am] = pa0.w;
        As[(ak+4)*132 + am] = pa1.x; As[(ak+5)*132 + am] = pa1.y;
        As[(ak+6)*132 + am] = pa1.z; As[(ak+7)*132 + am] = pa1.w;
        *(float4*)&Bs[bk*132 + bn]     = pb0;
        *(float4*)&Bs[bk*132 + bn + 4] = pb1;
        __syncthreads();
        if (k0 + 16 < 1024) fetch(k0 + 16);
#pragma unroll
        for (int kk = 0; kk < 16; ++kk) {
            float4 a0 = *(float4*)&As[kk*132 + (ty << 3)];
            float4 a1 = *(float4*)&As[kk*132 + (ty << 3) + 4];
            float4 b0 = *(float4*)&Bs[kk*132 + (tx << 3)];
            float4 b1 = *(float4*)&Bs[kk*132 + (tx << 3) + 4];
            float av[8] = {a0.x,a0.y,a0.z,a0.w,a1.x,a1.y,a1.z,a1.w};
            float bv[8] = {b0.x,b0.y,b0.z,b0.w,b1.x,b1.y,b1.z,b1.w};
#pragma unroll
            for (int r = 0; r < 8; ++r)
#pragma unroll
                for (int c = 0; c < 8; ++c) acc[r][c] += av[r] * bv[c];
        }
        __syncthreads();
    }
#pragma unroll
    for (int r = 0; r < 8; ++r) {
        int m = m0 + (ty << 3) + r;
        size_t base = (size_t)m * 1024u + n0 + (tx << 3);
#pragma unroll
        for (int c = 0; c < 8; ++c) {
            int nn = n0 + (tx << 3) + c;
            OUT[base + c] = acc[r][c] + obias[nn];
        }
    }
}

// =====================================================================
extern "C" void kernel_launch(void* const* d_in, const int* in_sizes, int n_in,
                              void* d_out, int out_size) {
    const float* x    = (const float*)d_in[0];
    const float* gmem = (const float*)d_in[1];
    const float* cw   = (const float*)d_in[2];
    const float* cb   = (const float*)d_in[3];
    const float* mw   = (const float*)d_in[4];
    const float* mb   = (const float*)d_in[5];
    const float* ow   = (const float*)d_in[6];
    const float* ob   = (const float*)d_in[7];
    float* out = (float*)d_out;

    float *pL, *pG, *pBC, *pM, *pCOMP;
    cudaGetSymbolAddress((void**)&pL,    g_L);
    cudaGetSymbolAddress((void**)&pG,    g_G);
    cudaGetSymbolAddress((void**)&pBC,   g_BC);
    cudaGetSymbolAddress((void**)&pM,    g_M);
    cudaGetSymbolAddress((void**)&pCOMP, g_COMP);

    const int BC_SMEM = 2 * 16384 * 4;       // 128 KB
    const int WA_SMEM = 20672 * 4;           // ~81 KB
    const int GA_SMEM = 24768 * 4;           // ~97 KB
    cudaFuncSetAttribute(bc_kernel, cudaFuncAttributeMaxDynamicSharedMemorySize, BC_SMEM);
    cudaFuncSetAttribute(win_attn,  cudaFuncAttributeMaxDynamicSharedMemorySize, WA_SMEM);
    cudaFuncSetAttribute(gattn,     cudaFuncAttributeMaxDynamicSharedMemorySize, GA_SMEM);

    bc_kernel  <<<dim3(256, 2), 512, BC_SMEM>>>(x, pBC);
    conv_kernel<<<64, 256>>>(x, cw, cb, pCOMP);
    win_attn   <<<dim3(8, 8, 16), 256, WA_SMEM>>>(x, pL, 0);
    win_attn   <<<dim3(8, 7, 16), 256, WA_SMEM>>>(x, pL, 1);
    norm_local <<<8192, 256>>>(pL);
    gattn      <<<dim3(128, 8, 2), 256, GA_SMEM>>>(x, gmem, pCOMP, pG);
    gemm_mix   <<<dim3(64, 8), 256>>>(pL, pG, pBC, mw, mb, pM);
    gemm_out   <<<dim3(64, 8), 256>>>(pM, ow, ob, out);
}

// round 3
// speedup vs baseline: 2.1376x; 2.1376x over previous
#include <cuda_runtime.h>
#include <math.h>
#include <stdint.h>

__device__ float g_L [2u*4096u*1024u];
__device__ float g_G [2u*4096u*1024u];
__device__ float g_BC[2u*4096u*1024u];
__device__ float g_M [2u*4096u*1024u];
__device__ float g_COMP[2u*64u*1024u];

__device__ __forceinline__ uint32_t f2tf(float x) {
    uint32_t u; asm("cvt.rn.tf32.f32 %0, %1;" : "=r"(u) : "f"(x)); return u;
}
__device__ __forceinline__ void mma8(float* c, const uint32_t* a, const uint32_t* b) {
    asm volatile("mma.sync.aligned.m16n8k8.row.col.f32.tf32.tf32.f32 "
        "{%0,%1,%2,%3}, {%4,%5,%6,%7}, {%8,%9}, {%0,%1,%2,%3};"
        : "+f"(c[0]), "+f"(c[1]), "+f"(c[2]), "+f"(c[3])
        : "r"(a[0]), "r"(a[1]), "r"(a[2]), "r"(a[3]), "r"(b[0]), "r"(b[1]));
}

// ============ 1) broadcast diffusion ============
__global__ void bc_kernel(const float* __restrict__ x, float* __restrict__ bc) {
    extern __shared__ float sm[];
    float* bufA = sm; float* bufB = sm + 16384;
    const int tid = threadIdx.x, b = blockIdx.y, d0 = blockIdx.x << 2;
    const float* src = x + (size_t)b * 4194304u + d0;
    for (int s = tid; s < 4096; s += 512)
        *(float4*)&bufA[s << 2] = *(const float4*)(src + (size_t)s * 1024u);
    __syncthreads();
    float acc[32];
#pragma unroll
    for (int e = 0; e < 32; ++e) acc[e] = 0.f;
    float* cur = bufA; float* nxt = bufB;
    for (int st = 1; st < 4096; st <<= 1) {
#pragma unroll
        for (int q = 0; q < 8; ++q) {
            int s = tid + (q << 9), sc = s << 2;
            int sm1 = ((s - st) & 4095) << 2, sp1 = ((s + st) & 4095) << 2;
#pragma unroll
            for (int j = 0; j < 4; ++j) {
                float v = cur[sc + j] + 0.5f * (cur[sm1 + j] + cur[sp1 + j]);
                nxt[sc + j] = v;
                acc[(q << 2) + j] += v;
            }
        }
        __syncthreads();
        float* t = cur; cur = nxt; nxt = t;
    }
    const float inv = 1.0f / 13.0f;
    float* dst = bc + (size_t)b * 4194304u + d0;
#pragma unroll
    for (int q = 0; q < 8; ++q) {
        int s = tid + (q << 9);
        *(float4*)(dst + (size_t)s * 1024u) =
            make_float4(acc[q*4]*inv, acc[q*4+1]*inv, acc[q*4+2]*inv, acc[q*4+3]*inv);
    }
}

// ============ 2) conv1d(k=4,s=4), first 64 tokens ============
__global__ void __launch_bounds__(256) conv_kernel(
        const float* __restrict__ x, const float* __restrict__ cw,
        const float* __restrict__ cb, float* __restrict__ comp) {
    __shared__ float As[32 * 129];
    __shared__ float Ws[32 * 20];
    const int tid = threadIdx.x, o0 = blockIdx.x << 4;
    const int mb = (tid & 31) << 2, og = (tid >> 5) << 1;
    float acc[4][2];
#pragma unroll
    for (int r = 0; r < 4; ++r) { acc[r][0] = 0.f; acc[r][1] = 0.f; }
    for (int k0 = 0; k0 < 4096; k0 += 32) {
        __syncthreads();
#pragma unroll
        for (int it = 0; it < 16; ++it) {
            int idx = tid + (it << 8);
            int m = idx & 127, kc = idx >> 7, k = k0 + kc;
            int bb = m >> 6, t = m & 63;
            As[kc * 129 + m] =
                x[(size_t)bb * 4194304u + (size_t)((t << 2) + (k & 3)) * 1024u + (k >> 2)];
        }
#pragma unroll
        for (int it = 0; it < 2; ++it) {
            int idx = tid + (it << 8);
            int oo = idx >> 5, kc = idx & 31;
            Ws[kc * 20 + oo] = cw[(size_t)(o0 + oo) * 4096u + k0 + kc];
        }
        __syncthreads();
#pragma unroll
        for (int kc = 0; kc < 32; ++kc) {
            float a0 = As[kc*129+mb], a1 = As[kc*129+mb+1];
            float a2 = As[kc*129+mb+2], a3 = As[kc*129+mb+3];
            float w0 = Ws[kc*20+og], w1 = Ws[kc*20+og+1];
            acc[0][0]+=a0*w0; acc[0][1]+=a0*w1; acc[1][0]+=a1*w0; acc[1][1]+=a1*w1;
            acc[2][0]+=a2*w0; acc[2][1]+=a2*w1; acc[3][0]+=a3*w0; acc[3][1]+=a3*w1;
        }
    }
#pragma unroll
    for (int r = 0; r < 4; ++r)
#pragma unroll
        for (int c = 0; c < 2; ++c) {
            int m = mb + r, o = o0 + og + c;
            comp[(size_t)m * 1024u + o] = acc[r][c] + cb[o];
        }
}

// ============ 3) sliding-window attention v2 ============
__global__ void __launch_bounds__(256) win_attn(
        const float* __restrict__ x, float* __restrict__ L, int parity) {
    extern __shared__ float sm[];
    float* Qs = sm;            // 64*132
    float* Ks = sm + 8448;     // 64*132
    float* Ss = sm + 16896;    // 64*65
    float* Al = sm + 21056;    // 64
    const int tid = threadIdx.x;
    const int qt = blockIdx.x;
    const int n = (blockIdx.y << 1) + parity;
    const int b = blockIdx.z >> 3, h = blockIdx.z & 7;
    const int base = n << 8, q0 = base + (qt << 6);
    const float* xb = x + (size_t)b * 4194304u + (h << 7);
#pragma unroll
    for (int it = 0; it < 8; ++it) {
        int i = tid + (it << 8);
        int r = i >> 5, c4 = (i & 31) << 2;
        *(float4*)&Qs[r * 132 + c4] = *(const float4*)(xb + (size_t)(q0 + r) * 1024u + c4);
    }
    const int qb = (tid >> 4) << 2, kb = (tid & 15) << 2;
    const int dg = tid & 15, cA = dg << 2, cB = 64 + (dg << 2);
    const int row = tid >> 2, seg = tid & 3;
    const float scale = 0.08838834764831845f;
    float acc[4][8];
#pragma unroll
    for (int r = 0; r < 4; ++r)
#pragma unroll
        for (int c = 0; c < 8; ++c) acc[r][c] = 0.f;
    float m_i = -1e30f, l_i = 0.f;

    for (int kt = 0; kt < 8; ++kt) {
        __syncthreads();
        int k0 = base + (kt << 6);
#pragma unroll
        for (int it = 0; it < 8; ++it) {
            int i = tid + (it << 8);
            int r = i >> 5, c4 = (i & 31) << 2;
            *(float4*)&Ks[r * 132 + c4] = *(const float4*)(xb + (size_t)(k0 + r) * 1024u + c4);
        }
        __syncthreads();
        // scores 4x4
        float s4[4][4];
#pragma unroll
        for (int r = 0; r < 4; ++r)
#pragma unroll
            for (int c = 0; c < 4; ++c) s4[r][c] = 0.f;
#pragma unroll 4
        for (int d = 0; d < 128; ++d) {
            float qv[4], kv[4];
#pragma unroll
            for (int r = 0; r < 4; ++r) qv[r] = Qs[(qb + r) * 132 + d];
#pragma unroll
            for (int c = 0; c < 4; ++c) kv[c] = Ks[(kb + c) * 132 + d];
#pragma unroll
            for (int r = 0; r < 4; ++r)
#pragma unroll
                for (int c = 0; c < 4; ++c) s4[r][c] += qv[r] * kv[c];
        }
#pragma unroll
        for (int r = 0; r < 4; ++r)
#pragma unroll
            for (int c = 0; c < 4; ++c)
                Ss[(qb + r) * 65 + kb + c] = s4[r][c] * scale;
        __syncthreads();
        // softmax: exp once, stored back
        float* srow = &Ss[row * 65 + (seg << 4)];
        float mt = -1e30f;
#pragma unroll
        for (int jj = 0; jj < 16; ++jj) mt = fmaxf(mt, srow[jj]);
        mt = fmaxf(mt, __shfl_xor_sync(0xffffffffu, mt, 1));
        mt = fmaxf(mt, __shfl_xor_sync(0xffffffffu, mt, 2));
        float m_new = fmaxf(m_i, mt);
        float alpha = __expf(m_i - m_new);
        float ls = 0.f;
#pragma unroll
        for (int jj = 0; jj < 16; ++jj) {
            float p = __expf(srow[jj] - m_new);
            srow[jj] = p; ls += p;
        }
        ls += __shfl_xor_sync(0xffffffffu, ls, 1);
        ls += __shfl_xor_sync(0xffffffffu, ls, 2);
        l_i = l_i * alpha + ls;
        m_i = m_new;
        if (seg == 0) Al[row] = alpha;
        __syncthreads();
        // AV: 4q x 8d
#pragma unroll
        for (int r = 0; r < 4; ++r) {
            float a = Al[qb + r];
#pragma unroll
            for (int c = 0; c < 8; ++c) acc[r][c] *= a;
        }
#pragma unroll 2
        for (int j = 0; j < 64; ++j) {
            const float* vr = &Ks[j * 132];
            float4 v = *(const float4*)(vr + cA);
            float4 w = *(const float4*)(vr + cB);
#pragma unroll
            for (int r = 0; r < 4; ++r) {
                float p = Ss[(qb + r) * 65 + j];
                acc[r][0] += p * v.x; acc[r][1] += p * v.y;
                acc[r][2] += p * v.z; acc[r][3] += p * v.w;
                acc[r][4] += p * w.x; acc[r][5] += p * w.y;
                acc[r][6] += p * w.z; acc[r][7] += p * w.w;
            }
        }
    }
    __syncthreads();
    if (seg == 0) Al[row] = 1.0f / l_i;
    __syncthreads();
#pragma unroll
    for (int r = 0; r < 4; ++r) {
        float tw = (0.5f + (float)((qt << 6) + qb + r) * (1.0f / 511.0f)) * Al[qb + r];
        float* dst = L + ((size_t)b * 4096u + q0 + qb + r) * 1024u + (h << 7);
        if (parity == 0) {
            *(float4*)(dst + cA) = make_float4(acc[r][0]*tw, acc[r][1]*tw, acc[r][2]*tw, acc[r][3]*tw);
            *(float4*)(dst + cB) = make_float4(acc[r][4]*tw, acc[r][5]*tw, acc[r][6]*tw, acc[r][7]*tw);
        } else {
            float4 o = *(float4*)(dst + cA);
            o.x += acc[r][0]*tw; o.y += acc[r][1]*tw; o.z += acc[r][2]*tw; o.w += acc[r][3]*tw;
            *(float4*)(dst + cA) = o;
            float4 p = *(float4*)(dst + cB);
            p.x += acc[r][4]*tw; p.y += acc[r][5]*tw; p.z += acc[r][6]*tw; p.w += acc[r][7]*tw;
            *(float4*)(dst + cB) = p;
        }
    }
}

__device__ __forceinline__ float invden(int s) {
    int n1 = s >> 8, i1 = s & 255;
    float d = 0.f;
    if (n1 <= 14) d += 0.5f + (float)i1 * (1.0f / 511.0f);
    if (n1 >= 1)  d += 0.5f + (float)(i1 + 256) * (1.0f / 511.0f);
    return 1.0f / d;
}
__global__ void norm_local(float* __restrict__ L) {
    size_t i = (size_t)blockIdx.x * blockDim.x + threadIdx.x;
    int s = (int)((i >> 8) & 4095);
    float inv = invden(s);
    float4* p = (float4*)L;
    float4 v = p[i];
    v.x *= inv; v.y *= inv; v.z *= inv; v.w *= inv;
    p[i] = v;
}

// ============ 4) compressed-global attention ============
__global__ void __launch_bounds__(256) gattn(
        const float* __restrict__ x, const float* __restrict__ gmem,
        const float* __restrict__ comp, float* __restrict__ G) {
    extern __shared__ float sm[];
    float* KVs = sm;             // 128*129
    float* Qs  = sm + 16512;     // 32*129
    float* Ps  = sm + 20640;     // 32*129
    const int tid = threadIdx.x;
    const int s0 = blockIdx.x << 5, h = blockIdx.y, b = blockIdx.z;
#pragma unroll
    for (int it = 0; it < 16; ++it) {
        int i = tid + (it << 8);
        int r = i >> 5, c4 = (i & 31) << 2;
        float4 v;
        if (r < 64) v = *(const float4*)(comp + (size_t)((b << 6) + r) * 1024u + (h << 7) + c4);
        else        v = *(const float4*)(gmem + (size_t)((h << 6) + (r - 64)) * 128u + c4);
        float* kv = &KVs[r * 129 + c4];
        kv[0] = v.x; kv[1] = v.y; kv[2] = v.z; kv[3] = v.w;
    }
#pragma unroll
    for (int it = 0; it < 4; ++it) {
        int i = tid + (it << 8);
        int r = i >> 5, c4 = (i & 31) << 2;
        float4 v = *(const float4*)(x + (size_t)b * 4194304u + (size_t)(s0 + r) * 1024u + (h << 7) + c4);
        float* q = &Qs[r * 129 + c4];
        q[0] = v.x; q[1] = v.y; q[2] = v.z; q[3] = v.w;
    }
    __syncthreads();
    {
        const int qb = (tid & 7) << 2, tb = (tid >> 3) << 2;
        float s4[4][4];
#pragma unroll
        for (int r = 0; r < 4; ++r)
#pragma unroll
            for (int c = 0; c < 4; ++c) s4[r][c] = 0.f;
#pragma unroll 4
        for (int d = 0; d < 128; ++d) {
            float qv[4], kv[4];
#pragma unroll
            for (int r = 0; r < 4; ++r) qv[r] = Qs[(qb + r) * 129 + d];
#pragma unroll
            for (int c = 0; c < 4; ++c) kv[c] = KVs[(tb + c) * 129 + d];
#pragma unroll
            for (int r = 0; r < 4; ++r)
#pragma unroll
                for (int c = 0; c < 4; ++c) s4[r][c] += qv[r] * kv[c];
        }
        const float scale = 0.08838834764831845f;
#pragma unroll
        for (int r = 0; r < 4; ++r)
#pragma unroll
            for (int c = 0; c < 4; ++c)
                Ps[(qb + r) * 129 + tb + c] = s4[r][c] * scale;
    }
    __syncthreads();
    {
        int lane = tid & 31, wid = tid >> 5;
        int row = (wid << 2) + (lane >> 3);
        int c0 = (lane & 7) << 4;
        float* pr = &Ps[row * 129 + c0];
        float mt = -1e30f;
        float pv[16];
#pragma unroll
        for (int jj = 0; jj < 16; ++jj) mt = fmaxf(mt, pr[jj]);
        mt = fmaxf(mt, __shfl_xor_sync(0xffffffffu, mt, 1));
        mt = fmaxf(mt, __shfl_xor_sync(0xffffffffu, mt, 2));
        mt = fmaxf(mt, __shfl_xor_sync(0xffffffffu, mt, 4));
        float ssum = 0.f;
#pragma unroll
        for (int jj = 0; jj < 16; ++jj) { pv[jj] = __expf(pr[jj] - mt); ssum += pv[jj]; }
        ssum += __shfl_xor_sync(0xffffffffu, ssum, 1);
        ssum += __shfl_xor_sync(0xffffffffu, ssum, 2);
        ssum += __shfl_xor_sync(0xffffffffu, ssum, 4);
        float invs = 1.0f / ssum;
#pragma unroll
        for (int jj = 0; jj < 16; ++jj) pr[jj] = pv[jj] * invs;
    }
    __syncthreads();
    {
        const int qg = (tid & 7) << 2, dgp = (tid >> 3) << 2;
        float o4[4][4];
#pragma unroll
        for (int r = 0; r < 4; ++r)
#pragma unroll
            for (int c = 0; c < 4; ++c) o4[r][c] = 0.f;
#pragma unroll 4
        for (int t = 0; t < 128; ++t) {
            float pv[4], kv[4];
#pragma unroll
            for (int r = 0; r < 4; ++r) pv[r] = Ps[(qg + r) * 129 + t];
#pragma unroll
            for (int c = 0; c < 4; ++c) kv[c] = KVs[t * 129 + dgp + c];
#pragma unroll
            for (int r = 0; r < 4; ++r)
#pragma unroll
                for (int c = 0; c < 4; ++c) o4[r][c] += pv[r] * kv[c];
        }
#pragma unroll
        for (int r = 0; r < 4; ++r)
            *(float4*)(G + ((size_t)b * 4096u + s0 + qg + r) * 1024u + (h << 7) + dgp) =
                make_float4(o4[r][0], o4[r][1], o4[r][2], o4[r][3]);
    }
}

// ============ 5+6) tensor-core tf32 GEMM (mma.sync m16n8k8) ============
// mode 0: C = A0 @ W + bias           (K = 1024)
// mode 1: C = gate-mix of [L,G] @ W   (K = 2048)
__global__ void __launch_bounds__(256) gemm_tc(
        int mode, const float* __restrict__ A0, const float* __restrict__ A1,
        const float* __restrict__ BCp, const float* __restrict__ W,
        const float* __restrict__ bias, float* __restrict__ C, int K) {
    __shared__ uint32_t As[128 * 36];   // [m][k], pitch 36
    __shared__ uint32_t Bs[32 * 136];   // [k][n], pitch 136
    const int tid = threadIdx.x;
    const int m0 = blockIdx.x << 7, n0 = blockIdx.y << 7;
    const int wid = tid >> 5, lane = tid & 31;
    const int quad = lane >> 2, tq = lane & 3;
    const int wm = wid >> 2, wn = wid & 3;       // 2 x 4 warp grid
    // loaders
    const int am = tid >> 1, ak = (tid & 1) << 4;      // A: row am, 16 k from ak
    const int bk = tid >> 3, bn = (tid & 7) << 4;      // B: row bk, 16 n from bn

    float acc[4][4][4];
#pragma unroll
    for (int i = 0; i < 4; ++i)
#pragma unroll
        for (int j = 0; j < 4; ++j)
#pragma unroll
            for (int e = 0; e < 4; ++e) acc[i][j][e] = 0.f;

    float4 pa[4], pb[4];
    auto fetch = [&](int kt) {
        const float* asrc = (mode == 1 && kt >= 1024)
            ? (A1 + (size_t)(m0 + am) * 1024u + (kt - 1024) + ak)
            : (A0 + (size_t)(m0 + am) * 1024u + kt + ak);
#pragma unroll
        for (int q = 0; q < 4; ++q) pa[q] = *(const float4*)(asrc + (q << 2));
        const float* bsrc = W + (size_t)(kt + bk) * 1024u + n0 + bn;
#pragma unroll
        for (int q = 0; q < 4; ++q) pb[q] = *(const float4*)(bsrc + (q << 2));
    };
    fetch(0);
    for (int kt = 0; kt < K; kt += 32) {
#pragma unroll
        for (int q = 0; q < 4; ++q) {
            uint32_t* d = &As[am * 36 + ak + (q << 2)];
            d[0] = f2tf(pa[q].x); d[1] = f2tf(pa[q].y); d[2] = f2tf(pa[q].z); d[3] = f2tf(pa[q].w);
            uint32_t* e = &Bs[bk * 136 + bn + (q << 2)];
            e[0] = f2tf(pb[q].x); e[1] = f2tf(pb[q].y); e[2] = f2tf(pb[q].z); e[3] = f2tf(pb[q].w);
        }
        __syncthreads();
        if (kt + 32 < K) fetch(kt + 32);
#pragma unroll
        for (int ks = 0; ks < 4; ++ks) {
            const int k0 = ks << 3;
            uint32_t af[4][4], bf[4][2];
#pragma unroll
            for (int i = 0; i < 4; ++i) {
                int r = (wm << 6) + (i << 4) + quad;
                af[i][0] = As[r * 36 + k0 + tq];
                af[i][1] = As[(r + 8) * 36 + k0 + tq];
                af[i][2] = As[r * 36 + k0 + tq + 4];
                af[i][3] = As[(r + 8) * 36 + k0 + tq + 4];
            }
#pragma unroll
            for (int j = 0; j < 4; ++j) {
                int cidx = (wn << 5) + (j << 3) + quad;
                bf[j][0] = Bs[(k0 + tq) * 136 + cidx];
                bf[j][1] = Bs[(k0 + tq + 4) * 136 + cidx];
            }
#pragma unroll
            for (int i = 0; i < 4; ++i)
#pragma unroll
                for (int j = 0; j < 4; ++j) mma8(acc[i][j], af[i], bf[j]);
        }
        __syncthreads();
    }
    // epilogue
#pragma unroll
    for (int i = 0; i < 4; ++i)
#pragma unroll
        for (int j = 0; j < 4; ++j) {
            int mr = m0 + (wm << 6) + (i << 4) + quad;
            int nc = n0 + (wn << 5) + (j << 3) + (tq << 1);
#pragma unroll
            for (int hf = 0; hf < 2; ++hf) {
                int m = mr + (hf << 3);
                size_t bix = (size_t)m * 1024u + nc;
#pragma unroll
                for (int e = 0; e < 2; ++e) {
                    float z = acc[i][j][(hf << 1) + e] + bias[nc + e];
                    if (mode == 1) {
                        float g = 1.0f / (1.0f + __expf(-z));
                        C[bix + e] = g * A0[bix + e] + (1.0f - g) * A1[bix + e] + BCp[bix + e];
                    } else {
                        C[bix + e] = z;
                    }
                }
            }
        }
}

// =====================================================================
extern "C" void kernel_launch(void* const* d_in, const int* in_sizes, int n_in,
                              void* d_out, int out_size) {
    const float* x    = (const float*)d_in[0];
    const float* gmem = (const float*)d_in[1];
    const float* cw   = (const float*)d_in[2];
    const float* cb   = (const float*)d_in[3];
    const float* mw   = (const float*)d_in[4];
    const float* mb   = (const float*)d_in[5];
    const float* ow   = (const float*)d_in[6];
    const float* ob   = (const float*)d_in[7];
    float* out = (float*)d_out;

    float *pL, *pG, *pBC, *pM, *pCOMP;
    cudaGetSymbolAddress((void**)&pL,    g_L);
    cudaGetSymbolAddress((void**)&pG,    g_G);
    cudaGetSymbolAddress((void**)&pBC,   g_BC);
    cudaGetSymbolAddress((void**)&pM,    g_M);
    cudaGetSymbolAddress((void**)&pCOMP, g_COMP);

    const int BC_SMEM = 2 * 16384 * 4;
    const int WA_SMEM = 21120 * 4;
    const int GA_SMEM = 24768 * 4;
    cudaFuncSetAttribute(bc_kernel, cudaFuncAttributeMaxDynamicSharedMemorySize, BC_SMEM);
    cudaFuncSetAttribute(win_attn,  cudaFuncAttributeMaxDynamicSharedMemorySize, WA_SMEM);
    cudaFuncSetAttribute(gattn,     cudaFuncAttributeMaxDynamicSharedMemorySize, GA_SMEM);

    bc_kernel  <<<dim3(256, 2), 512, BC_SMEM>>>(x, pBC);
    conv_kernel<<<64, 256>>>(x, cw, cb, pCOMP);
    win_attn   <<<dim3(8, 8, 16), 256, WA_SMEM>>>(x, pL, 0);
    win_attn   <<<dim3(8, 7, 16), 256, WA_SMEM>>>(x, pL, 1);
    norm_local <<<8192, 256>>>(pL);
    gattn      <<<dim3(128, 8, 2), 256, GA_SMEM>>>(x, gmem, pCOMP, pG);
    gemm_tc    <<<dim3(64, 8), 256>>>(1, pL, pG, pBC, mw, mb, pM, 2048);
    gemm_tc    <<<dim3(64, 8), 256>>>(0, pM, pM, pBC, ow, ob, out, 1024);
}

// round 4
// speedup vs baseline: 3.1701x; 1.4830x over previous
#include <cuda_runtime.h>
#include <math.h>
#include <stdint.h>

__device__ float g_L [2u*4096u*1024u];
__device__ float g_G [2u*4096u*1024u];
__device__ float g_BC[2u*4096u*1024u];
__device__ float g_M [2u*4096u*1024u];
__device__ float g_COMP[2u*64u*1024u];

__device__ __forceinline__ uint32_t f2tf(float x) {
    uint32_t u; asm("cvt.rn.tf32.f32 %0, %1;" : "=r"(u) : "f"(x)); return u;
}
__device__ __forceinline__ float f2tff(float x) {
    uint32_t u; asm("cvt.rn.tf32.f32 %0, %1;" : "=r"(u) : "f"(x));
    return __uint_as_float(u);
}
__device__ __forceinline__ void mma8(float* c, const uint32_t* a, const uint32_t* b) {
    asm volatile("mma.sync.aligned.m16n8k8.row.col.f32.tf32.tf32.f32 "
        "{%0,%1,%2,%3}, {%4,%5,%6,%7}, {%8,%9}, {%0,%1,%2,%3};"
        : "+f"(c[0]), "+f"(c[1]), "+f"(c[2]), "+f"(c[3])
        : "r"(a[0]), "r"(a[1]), "r"(a[2]), "r"(a[3]), "r"(b[0]), "r"(b[1]));
}

// ============ 1) broadcast diffusion ============
__global__ void bc_kernel(const float* __restrict__ x, float* __restrict__ bc) {
    extern __shared__ float sm[];
    float* bufA = sm; float* bufB = sm + 16384;
    const int tid = threadIdx.x, b = blockIdx.y, d0 = blockIdx.x << 2;
    const float* src = x + (size_t)b * 4194304u + d0;
    for (int s = tid; s < 4096; s += 512)
        *(float4*)&bufA[s << 2] = *(const float4*)(src + (size_t)s * 1024u);
    __syncthreads();
    float acc[32];
#pragma unroll
    for (int e = 0; e < 32; ++e) acc[e] = 0.f;
    float* cur = bufA; float* nxt = bufB;
    for (int st = 1; st < 4096; st <<= 1) {
#pragma unroll
        for (int q = 0; q < 8; ++q) {
            int s = tid + (q << 9), sc = s << 2;
            int sm1 = ((s - st) & 4095) << 2, sp1 = ((s + st) & 4095) << 2;
#pragma unroll
            for (int j = 0; j < 4; ++j) {
                float v = cur[sc + j] + 0.5f * (cur[sm1 + j] + cur[sp1 + j]);
                nxt[sc + j] = v;
                acc[(q << 2) + j] += v;
            }
        }
        __syncthreads();
        float* t = cur; cur = nxt; nxt = t;
    }
    const float inv = 1.0f / 13.0f;
    float* dst = bc + (size_t)b * 4194304u + d0;
#pragma unroll
    for (int q = 0; q < 8; ++q) {
        int s = tid + (q << 9);
        *(float4*)(dst + (size_t)s * 1024u) =
            make_float4(acc[q*4]*inv, acc[q*4+1]*inv, acc[q*4+2]*inv, acc[q*4+3]*inv);
    }
}

// ============ 2) conv1d(k=4,s=4), first 64 tokens ============
__global__ void __launch_bounds__(256) conv_kernel(
        const float* __restrict__ x, const float* __restrict__ cw,
        const float* __restrict__ cb, float* __restrict__ comp) {
    __shared__ float As[32 * 129];
    __shared__ float Ws[32 * 20];
    const int tid = threadIdx.x, o0 = blockIdx.x << 4;
    const int mb = (tid & 31) << 2, og = (tid >> 5) << 1;
    float acc[4][2];
#pragma unroll
    for (int r = 0; r < 4; ++r) { acc[r][0] = 0.f; acc[r][1] = 0.f; }
    for (int k0 = 0; k0 < 4096; k0 += 32) {
        __syncthreads();
#pragma unroll
        for (int it = 0; it < 16; ++it) {
            int idx = tid + (it << 8);
            int m = idx & 127, kc = idx >> 7, k = k0 + kc;
            int bb = m >> 6, t = m & 63;
            As[kc * 129 + m] =
                x[(size_t)bb * 4194304u + (size_t)((t << 2) + (k & 3)) * 1024u + (k >> 2)];
        }
#pragma unroll
        for (int it = 0; it < 2; ++it) {
            int idx = tid + (it << 8);
            int oo = idx >> 5, kc = idx & 31;
            Ws[kc * 20 + oo] = cw[(size_t)(o0 + oo) * 4096u + k0 + kc];
        }
        __syncthreads();
#pragma unroll
        for (int kc = 0; kc < 32; ++kc) {
            float a0 = As[kc*129+mb], a1 = As[kc*129+mb+1];
            float a2 = As[kc*129+mb+2], a3 = As[kc*129+mb+3];
            float w0 = Ws[kc*20+og], w1 = Ws[kc*20+og+1];
            acc[0][0]+=a0*w0; acc[0][1]+=a0*w1; acc[1][0]+=a1*w0; acc[1][1]+=a1*w1;
            acc[2][0]+=a2*w0; acc[2][1]+=a2*w1; acc[3][0]+=a3*w0; acc[3][1]+=a3*w1;
        }
    }
#pragma unroll
    for (int r = 0; r < 4; ++r)
#pragma unroll
        for (int c = 0; c < 2; ++c) {
            int m = mb + r, o = o0 + og + c;
            comp[(size_t)m * 1024u + o] = acc[r][c] + cb[o];
        }
}

// ============ 3) sliding-window attention v3: tensor cores ============
// smem: Qs[64][132] tf32, Vt[128][72] tf32 (Vt[d][t]=K[t][d]), Ss[64][68], Al[64]
__global__ void __launch_bounds__(256) win_attn(
        const float* __restrict__ x, float* __restrict__ L, int parity) {
    extern __shared__ float sm[];
    float* Qs = sm;              // 8448
    float* Vt = sm + 8448;       // 9216
    float* Ss = sm + 17664;      // 4352
    float* Al = sm + 22016;      // 64
    const int tid = threadIdx.x;
    const int lane = tid & 31, wid = tid >> 5;
    const int g = lane >> 2, tq = lane & 3;
    const int qt = blockIdx.x;
    const int n = (blockIdx.y << 1) + parity;
    const int b = blockIdx.z >> 3, h = blockIdx.z & 7;
    const int base = n << 8, q0 = base + (qt << 6);
    const float* xb = x + (size_t)b * 4194304u + (h << 7);

    // load Q (coalesced), convert to tf32 at store
#pragma unroll
    for (int it = 0; it < 8; ++it) {
        int i = tid + (it << 8);
        int r = i >> 5, c4 = (i & 31) << 2;
        float4 v = *(const float4*)(xb + (size_t)(q0 + r) * 1024u + c4);
        float* q = &Qs[r * 132 + c4];
        q[0] = f2tff(v.x); q[1] = f2tff(v.y); q[2] = f2tff(v.z); q[3] = f2tff(v.w);
    }

    const int wm = wid >> 1, wn = wid & 1;
    const int m0 = wm << 4;          // 16-row tile
    const int sn0 = wn << 5;         // score cols: 32 per warp
    const int on0 = wn << 6;         // AV cols: 64 per warp
    const int srow = tid >> 2, seg = tid & 3;
    const float scale = 0.08838834764831845f;

    float oacc[8][4];
#pragma unroll
    for (int nt = 0; nt < 8; ++nt)
#pragma unroll
        for (int e = 0; e < 4; ++e) oacc[nt][e] = 0.f;
    float m_i = -1e30f, l_i = 0.f;

    for (int kt = 0; kt < 8; ++kt) {
        __syncthreads();
        const int ktok = base + (kt << 6);
        // load K tile transposed (strided global reads, conflict-free STS)
#pragma unroll
        for (int it = 0; it < 8; ++it) {
            int i = tid + (it << 8);
            int t = i & 63, dq = i >> 6;
            float4 v = *(const float4*)(xb + (size_t)(ktok + t) * 1024u + (dq << 2));
            Vt[((dq << 2) + 0) * 72 + t] = f2tff(v.x);
            Vt[((dq << 2) + 1) * 72 + t] = f2tff(v.y);
            Vt[((dq << 2) + 2) * 72 + t] = f2tff(v.z);
            Vt[((dq << 2) + 3) * 72 + t] = f2tff(v.w);
        }
        __syncthreads();

        // ---- scores: S(64x64) = Q @ K^T ----
        float sacc[4][4];
#pragma unroll
        for (int nt = 0; nt < 4; ++nt)
#pragma unroll
            for (int e = 0; e < 4; ++e) sacc[nt][e] = 0.f;
#pragma unroll
        for (int kd = 0; kd < 128; kd += 8) {
            uint32_t a[4];
            a[0] = __float_as_uint(Qs[(m0 + g) * 132 + kd + tq]);
            a[1] = __float_as_uint(Qs[(m0 + g + 8) * 132 + kd + tq]);
            a[2] = __float_as_uint(Qs[(m0 + g) * 132 + kd + tq + 4]);
            a[3] = __float_as_uint(Qs[(m0 + g + 8) * 132 + kd + tq + 4]);
#pragma unroll
            for (int nt = 0; nt < 4; ++nt) {
                uint32_t bb[2];
                int tcol = sn0 + (nt << 3) + g;
                bb[0] = __float_as_uint(Vt[(kd + tq) * 72 + tcol]);
                bb[1] = __float_as_uint(Vt[(kd + tq + 4) * 72 + tcol]);
                mma8(sacc[nt], a, bb);
            }
        }
#pragma unroll
        for (int nt = 0; nt < 4; ++nt) {
            int nc = sn0 + (nt << 3) + (tq << 1);
            *(float2*)&Ss[(m0 + g) * 68 + nc] =
                make_float2(sacc[nt][0] * scale, sacc[nt][1] * scale);
            *(float2*)&Ss[(m0 + g + 8) * 68 + nc] =
                make_float2(sacc[nt][2] * scale, sacc[nt][3] * scale);
        }
        __syncthreads();

        // ---- online softmax; exp once; store P as tf32 ----
        {
            float* sr = &Ss[srow * 68 + (seg << 4)];
            float mt = -1e30f;
#pragma unroll
            for (int jj = 0; jj < 16; ++jj) mt = fmaxf(mt, sr[jj]);
            mt = fmaxf(mt, __shfl_xor_sync(0xffffffffu, mt, 1));
            mt = fmaxf(mt, __shfl_xor_sync(0xffffffffu, mt, 2));
            float m_new = fmaxf(m_i, mt);
            float alpha = __expf(m_i - m_new);
            float ls = 0.f;
#pragma unroll
            for (int jj = 0; jj < 16; ++jj) {
                float p = __expf(sr[jj] - m_new);
                ls += p;
                sr[jj] = f2tff(p);
            }
            ls += __shfl_xor_sync(0xffffffffu, ls, 1);
            ls += __shfl_xor_sync(0xffffffffu, ls, 2);
            l_i = l_i * alpha + ls;
            m_i = m_new;
            if (seg == 0) Al[srow] = alpha;
        }
        __syncthreads();

        // ---- AV: O(64x128) += P @ V ----
        float aLo = Al[m0 + g], aHi = Al[m0 + g + 8];
#pragma unroll
        for (int nt = 0; nt < 8; ++nt) {
            oacc[nt][0] *= aLo; oacc[nt][1] *= aLo;
            oacc[nt][2] *= aHi; oacc[nt][3] *= aHi;
        }
#pragma unroll
        for (int kd = 0; kd < 64; kd += 8) {
            uint32_t a[4];
            a[0] = __float_as_uint(Ss[(m0 + g) * 68 + kd + tq]);
            a[1] = __float_as_uint(Ss[(m0 + g + 8) * 68 + kd + tq]);
            a[2] = __float_as_uint(Ss[(m0 + g) * 68 + kd + tq + 4]);
            a[3] = __float_as_uint(Ss[(m0 + g + 8) * 68 + kd + tq + 4]);
#pragma unroll
            for (int nt = 0; nt < 8; ++nt) {
                uint32_t bb[2];
                int drow = on0 + (nt << 3) + g;
                bb[0] = __float_as_uint(Vt[drow * 72 + kd + tq]);
                bb[1] = __float_as_uint(Vt[drow * 72 + kd + tq + 4]);
                mma8(oacc[nt], a, bb);
            }
        }
    }
    __syncthreads();
    if (seg == 0) Al[srow] = 1.0f / l_i;
    __syncthreads();

    const float twLo = (0.5f + (float)((qt << 6) + m0 + g) * (1.0f / 511.0f)) * Al[m0 + g];
    const float twHi = (0.5f + (float)((qt << 6) + m0 + g + 8) * (1.0f / 511.0f)) * Al[m0 + g + 8];
    float* dLo = L + ((size_t)b * 4096u + q0 + m0 + g) * 1024u + (h << 7);
    float* dHi = dLo + (size_t)8 * 1024u;
#pragma unroll
    for (int nt = 0; nt < 8; ++nt) {
        int dc = on0 + (nt << 3) + (tq << 1);
        if (parity == 0) {
            *(float2*)(dLo + dc) = make_float2(oacc[nt][0] * twLo, oacc[nt][1] * twLo);
            *(float2*)(dHi + dc) = make_float2(oacc[nt][2] * twHi, oacc[nt][3] * twHi);
        } else {
            float2 o = *(float2*)(dLo + dc);
            o.x += oacc[nt][0] * twLo; o.y += oacc[nt][1] * twLo;
            *(float2*)(dLo + dc) = o;
            float2 p = *(float2*)(dHi + dc);
            p.x += oacc[nt][2] * twHi; p.y += oacc[nt][3] * twHi;
            *(float2*)(dHi + dc) = p;
        }
    }
}

__device__ __forceinline__ float invden(int s) {
    int n1 = s >> 8, i1 = s & 255;
    float d = 0.f;
    if (n1 <= 14) d += 0.5f + (float)i1 * (1.0f / 511.0f);
    if (n1 >= 1)  d += 0.5f + (float)(i1 + 256) * (1.0f / 511.0f);
    return 1.0f / d;
}
__global__ void norm_local(float* __restrict__ L) {
    size_t i = (size_t)blockIdx.x * blockDim.x + threadIdx.x;
    int s = (int)((i >> 8) & 4095);
    float inv = invden(s);
    float4* p = (float4*)L;
    float4 v = p[i];
    v.x *= inv; v.y *= inv; v.z *= inv; v.w *= inv;
    p[i] = v;
}

// ============ 4) compressed-global attention ============
__global__ void __launch_bounds__(256) gattn(
        const float* __restrict__ x, const float* __restrict__ gmem,
        const float* __restrict__ comp, float* __restrict__ G) {
    extern __shared__ float sm[];
    float* KVs = sm;             // 128*129
    float* Qs  = sm + 16512;     // 32*129
    float* Ps  = sm + 20640;     // 32*129
    const int tid = threadIdx.x;
    const int s0 = blockIdx.x << 5, h = blockIdx.y, b = blockIdx.z;
#pragma unroll
    for (int it = 0; it < 16; ++it) {
        int i = tid + (it << 8);
        int r = i >> 5, c4 = (i & 31) << 2;
        float4 v;
        if (r < 64) v = *(const float4*)(comp + (size_t)((b << 6) + r) * 1024u + (h << 7) + c4);
        else        v = *(const float4*)(gmem + (size_t)((h << 6) + (r - 64)) * 128u + c4);
        float* kv = &KVs[r * 129 + c4];
        kv[0] = v.x; kv[1] = v.y; kv[2] = v.z; kv[3] = v.w;
    }
#pragma unroll
    for (int it = 0; it < 4; ++it) {
        int i = tid + (it << 8);
        int r = i >> 5, c4 = (i & 31) << 2;
        float4 v = *(const float4*)(x + (size_t)b * 4194304u + (size_t)(s0 + r) * 1024u + (h << 7) + c4);
        float* q = &Qs[r * 129 + c4];
        q[0] = v.x; q[1] = v.y; q[2] = v.z; q[3] = v.w;
    }
    __syncthreads();
    {
        const int qb = (tid & 7) << 2, tb = (tid >> 3) << 2;
        float s4[4][4];
#pragma unroll
        for (int r = 0; r < 4; ++r)
#pragma unroll
            for (int c = 0; c < 4; ++c) s4[r][c] = 0.f;
#pragma unroll 4
        for (int d = 0; d < 128; ++d) {
            float qv[4], kv[4];
#pragma unroll
            for (int r = 0; r < 4; ++r) qv[r] = Qs[(qb + r) * 129 + d];
#pragma unroll
            for (int c = 0; c < 4; ++c) kv[c] = KVs[(tb + c) * 129 + d];
#pragma unroll
            for (int r = 0; r < 4; ++r)
#pragma unroll
                for (int c = 0; c < 4; ++c) s4[r][c] += qv[r] * kv[c];
        }
        const float scale = 0.08838834764831845f;
#pragma unroll
        for (int r = 0; r < 4; ++r)
#pragma unroll
            for (int c = 0; c < 4; ++c)
                Ps[(qb + r) * 129 + tb + c] = s4[r][c] * scale;
    }
    __syncthreads();
    {
        int lane = tid & 31, wd = tid >> 5;
        int row = (wd << 2) + (lane >> 3);
        int c0 = (lane & 7) << 4;
        float* pr = &Ps[row * 129 + c0];
        float mt = -1e30f;
        float pv[16];
#pragma unroll
        for (int jj = 0; jj < 16; ++jj) mt = fmaxf(mt, pr[jj]);
        mt = fmaxf(mt, __shfl_xor_sync(0xffffffffu, mt, 1));
        mt = fmaxf(mt, __shfl_xor_sync(0xffffffffu, mt, 2));
        mt = fmaxf(mt, __shfl_xor_sync(0xffffffffu, mt, 4));
        float ssum = 0.f;
#pragma unroll
        for (int jj = 0; jj < 16; ++jj) { pv[jj] = __expf(pr[jj] - mt); ssum += pv[jj]; }
        ssum += __shfl_xor_sync(0xffffffffu, ssum, 1);
        ssum += __shfl_xor_sync(0xffffffffu, ssum, 2);
        ssum += __shfl_xor_sync(0xffffffffu, ssum, 4);
        float invs = 1.0f / ssum;
#pragma unroll
        for (int jj = 0; jj < 16; ++jj) pr[jj] = pv[jj] * invs;
    }
    __syncthreads();
    {
        const int qg = (tid & 7) << 2, dgp = (tid >> 3) << 2;
        float o4[4][4];
#pragma unroll
        for (int r = 0; r < 4; ++r)
#pragma unroll
            for (int c = 0; c < 4; ++c) o4[r][c] = 0.f;
#pragma unroll 4
        for (int t = 0; t < 128; ++t) {
            float pv[4], kv[4];
#pragma unroll
            for (int r = 0; r < 4; ++r) pv[r] = Ps[(qg + r) * 129 + t];
#pragma unroll
            for (int c = 0; c < 4; ++c) kv[c] = KVs[t * 129 + dgp + c];
#pragma unroll
            for (int r = 0; r < 4; ++r)
#pragma unroll
                for (int c = 0; c < 4; ++c) o4[r][c] += pv[r] * kv[c];
        }
#pragma unroll
        for (int r = 0; r < 4; ++r)
            *(float4*)(G + ((size_t)b * 4096u + s0 + qg + r) * 1024u + (h << 7) + dgp) =
                make_float4(o4[r][0], o4[r][1], o4[r][2], o4[r][3]);
    }
}

// ============ 5+6) tensor-core tf32 GEMM ============
__global__ void __launch_bounds__(256) gemm_tc(
        int mode, const float* __restrict__ A0, const float* __restrict__ A1,
        const float* __restrict__ BCp, const float* __restrict__ W,
        const float* __restrict__ bias, float* __restrict__ C, int K) {
    __shared__ uint32_t As[128 * 36];
    __shared__ uint32_t Bs[32 * 136];
    const int tid = threadIdx.x;
    const int m0 = blockIdx.x << 7, n0 = blockIdx.y << 7;
    const int wid = tid >> 5, lane = tid & 31;
    const int quad = lane >> 2, tq = lane & 3;
    const int wm = wid >> 2, wn = wid & 3;
    const int am = tid >> 1, ak = (tid & 1) << 4;
    const int bk = tid >> 3, bn = (tid & 7) << 4;

    float acc[4][4][4];
#pragma unroll
    for (int i = 0; i < 4; ++i)
#pragma unroll
        for (int j = 0; j < 4; ++j)
#pragma unroll
            for (int e = 0; e < 4; ++e) acc[i][j][e] = 0.f;

    float4 pa[4], pb[4];
    auto fetch = [&](int kt) {
        const float* asrc = (mode == 1 && kt >= 1024)
            ? (A1 + (size_t)(m0 + am) * 1024u + (kt - 1024) + ak)
            : (A0 + (size_t)(m0 + am) * 1024u + kt + ak);
#pragma unroll
        for (int q = 0; q < 4; ++q) pa[q] = *(const float4*)(asrc + (q << 2));
        const float* bsrc = W + (size_t)(kt + bk) * 1024u + n0 + bn;
#pragma unroll
        for (int q = 0; q < 4; ++q) pb[q] = *(const float4*)(bsrc + (q << 2));
    };
    fetch(0);
    for (int kt = 0; kt < K; kt += 32) {
#pragma unroll
        for (int q = 0; q < 4; ++q) {
            uint32_t* d = &As[am * 36 + ak + (q << 2)];
            d[0] = f2tf(pa[q].x); d[1] = f2tf(pa[q].y); d[2] = f2tf(pa[q].z); d[3] = f2tf(pa[q].w);
            uint32_t* e = &Bs[bk * 136 + bn + (q << 2)];
            e[0] = f2tf(pb[q].x); e[1] = f2tf(pb[q].y); e[2] = f2tf(pb[q].z); e[3] = f2tf(pb[q].w);
        }
        __syncthreads();
        if (kt + 32 < K) fetch(kt + 32);
#pragma unroll
        for (int ks = 0; ks < 4; ++ks) {
            const int k0 = ks << 3;
            uint32_t af[4][4], bf[4][2];
#pragma unroll
            for (int i = 0; i < 4; ++i) {
                int r = (wm << 6) + (i << 4) + quad;
                af[i][0] = As[r * 36 + k0 + tq];
                af[i][1] = As[(r + 8) * 36 + k0 + tq];
                af[i][2] = As[r * 36 + k0 + tq + 4];
                af[i][3] = As[(r + 8) * 36 + k0 + tq + 4];
            }
#pragma unroll
            for (int j = 0; j < 4; ++j) {
                int cidx = (wn << 5) + (j << 3) + quad;
                bf[j][0] = Bs[(k0 + tq) * 136 + cidx];
                bf[j][1] = Bs[(k0 + tq + 4) * 136 + cidx];
            }
#pragma unroll
            for (int i = 0; i < 4; ++i)
#pragma unroll
                for (int j = 0; j < 4; ++j) mma8(acc[i][j], af[i], bf[j]);
        }
        __syncthreads();
    }
#pragma unroll
    for (int i = 0; i < 4; ++i)
#pragma unroll
        for (int j = 0; j < 4; ++j) {
            int mr = m0 + (wm << 6) + (i << 4) + quad;
            int nc = n0 + (wn << 5) + (j << 3) + (tq << 1);
#pragma unroll
            for (int hf = 0; hf < 2; ++hf) {
                int m = mr + (hf << 3);
                size_t bix = (size_t)m * 1024u + nc;
#pragma unroll
                for (int e = 0; e < 2; ++e) {
                    float z = acc[i][j][(hf << 1) + e] + bias[nc + e];
                    if (mode == 1) {
                        float gg = 1.0f / (1.0f + __expf(-z));
                        C[bix + e] = gg * A0[bix + e] + (1.0f - gg) * A1[bix + e] + BCp[bix + e];
                    } else {
                        C[bix + e] = z;
                    }
                }
            }
        }
}

// =====================================================================
extern "C" void kernel_launch(void* const* d_in, const int* in_sizes, int n_in,
                              void* d_out, int out_size) {
    const float* x    = (const float*)d_in[0];
    const float* gmem = (const float*)d_in[1];
    const float* cw   = (const float*)d_in[2];
    const float* cb   = (const float*)d_in[3];
    const float* mw   = (const float*)d_in[4];
    const float* mb   = (const float*)d_in[5];
    const float* ow   = (const float*)d_in[6];
    const float* ob   = (const float*)d_in[7];
    float* out = (float*)d_out;

    float *pL, *pG, *pBC, *pM, *pCOMP;
    cudaGetSymbolAddress((void**)&pL,    g_L);
    cudaGetSymbolAddress((void**)&pG,    g_G);
    cudaGetSymbolAddress((void**)&pBC,   g_BC);
    cudaGetSymbolAddress((void**)&pM,    g_M);
    cudaGetSymbolAddress((void**)&pCOMP, g_COMP);

    const int BC_SMEM = 2 * 16384 * 4;
    const int WA_SMEM = 22080 * 4;     // 88320 B
    const int GA_SMEM = 24768 * 4;
    cudaFuncSetAttribute(bc_kernel, cudaFuncAttributeMaxDynamicSharedMemorySize, BC_SMEM);
    cudaFuncSetAttribute(win_attn,  cudaFuncAttributeMaxDynamicSharedMemorySize, WA_SMEM);
    cudaFuncSetAttribute(gattn,     cudaFuncAttributeMaxDynamicSharedMemorySize, GA_SMEM);

    bc_kernel  <<<dim3(256, 2), 512, BC_SMEM>>>(x, pBC);
    conv_kernel<<<64, 256>>>(x, cw, cb, pCOMP);
    win_attn   <<<dim3(8, 8, 16), 256, WA_SMEM>>>(x, pL, 0);
    win_attn   <<<dim3(8, 7, 16), 256, WA_SMEM>>>(x, pL, 1);
    norm_local <<<8192, 256>>>(pL);
    gattn      <<<dim3(128, 8, 2), 256, GA_SMEM>>>(x, gmem, pCOMP, pG);
    gemm_tc    <<<dim3(64, 8), 256>>>(1, pL, pG, pBC, mw, mb, pM, 2048);
    gemm_tc    <<<dim3(64, 8), 256>>>(0, pM, pM, pBC, ow, ob, out, 1024);
}

// round 5
// speedup vs baseline: 3.5184x; 1.1099x over previous
#include <cuda_runtime.h>
#include <math.h>
#include <stdint.h>

__device__ float g_L [2u*4096u*1024u];
__device__ float g_G [2u*4096u*1024u];
__device__ float g_BC[2u*4096u*1024u];
__device__ float g_M [2u*4096u*1024u];
__device__ float g_COMP[2u*64u*1024u];

__device__ __forceinline__ uint32_t f2tf(float x) {
    uint32_t u; asm("cvt.rn.tf32.f32 %0, %1;" : "=r"(u) : "f"(x)); return u;
}
__device__ __forceinline__ float f2tff(float x) {
    uint32_t u; asm("cvt.rn.tf32.f32 %0, %1;" : "=r"(u) : "f"(x));
    return __uint_as_float(u);
}
__device__ __forceinline__ void mma8(float* c, const uint32_t* a, const uint32_t* b) {
    asm volatile("mma.sync.aligned.m16n8k8.row.col.f32.tf32.tf32.f32 "
        "{%0,%1,%2,%3}, {%4,%5,%6,%7}, {%8,%9}, {%0,%1,%2,%3};"
        : "+f"(c[0]), "+f"(c[1]), "+f"(c[2]), "+f"(c[3])
        : "r"(a[0]), "r"(a[1]), "r"(a[2]), "r"(a[3]), "r"(b[0]), "r"(b[1]));
}
__device__ __forceinline__ float invden(int s) {
    int n1 = s >> 8, i1 = s & 255;
    float d = 0.f;
    if (n1 <= 14) d += 0.5f + (float)i1 * (1.0f / 511.0f);
    if (n1 >= 1)  d += 0.5f + (float)(i1 + 256) * (1.0f / 511.0f);
    return 1.0f / d;
}

// ============ 1) broadcast diffusion ============
__global__ void bc_kernel(const float* __restrict__ x, float* __restrict__ bc) {
    extern __shared__ float sm[];
    float* bufA = sm; float* bufB = sm + 16384;
    const int tid = threadIdx.x, b = blockIdx.y, d0 = blockIdx.x << 2;
    const float* src = x + (size_t)b * 4194304u + d0;
    for (int s = tid; s < 4096; s += 512)
        *(float4*)&bufA[s << 2] = *(const float4*)(src + (size_t)s * 1024u);
    __syncthreads();
    float acc[32];
#pragma unroll
    for (int e = 0; e < 32; ++e) acc[e] = 0.f;
    float* cur = bufA; float* nxt = bufB;
    for (int st = 1; st < 4096; st <<= 1) {
#pragma unroll
        for (int q = 0; q < 8; ++q) {
            int s = tid + (q << 9), sc = s << 2;
            int sm1 = ((s - st) & 4095) << 2, sp1 = ((s + st) & 4095) << 2;
#pragma unroll
            for (int j = 0; j < 4; ++j) {
                float v = cur[sc + j] + 0.5f * (cur[sm1 + j] + cur[sp1 + j]);
                nxt[sc + j] = v;
                acc[(q << 2) + j] += v;
            }
        }
        __syncthreads();
        float* t = cur; cur = nxt; nxt = t;
    }
    const float inv = 1.0f / 13.0f;
    float* dst = bc + (size_t)b * 4194304u + d0;
#pragma unroll
    for (int q = 0; q < 8; ++q) {
        int s = tid + (q << 9);
        *(float4*)(dst + (size_t)s * 1024u) =
            make_float4(acc[q*4]*inv, acc[q*4+1]*inv, acc[q*4+2]*inv, acc[q*4+3]*inv);
    }
}

// ============ 2) conv1d(k=4,s=4), first 64 tokens ============
__global__ void __launch_bounds__(256) conv_kernel(
        const float* __restrict__ x, const float* __restrict__ cw,
        const float* __restrict__ cb, float* __restrict__ comp) {
    __shared__ float As[32 * 129];
    __shared__ float Ws[32 * 20];
    const int tid = threadIdx.x, o0 = blockIdx.x << 4;
    const int mb = (tid & 31) << 2, og = (tid >> 5) << 1;
    float acc[4][2];
#pragma unroll
    for (int r = 0; r < 4; ++r) { acc[r][0] = 0.f; acc[r][1] = 0.f; }
    for (int k0 = 0; k0 < 4096; k0 += 32) {
        __syncthreads();
#pragma unroll
        for (int it = 0; it < 16; ++it) {
            int idx = tid + (it << 8);
            int m = idx & 127, kc = idx >> 7, k = k0 + kc;
            int bb = m >> 6, t = m & 63;
            As[kc * 129 + m] =
                x[(size_t)bb * 4194304u + (size_t)((t << 2) + (k & 3)) * 1024u + (k >> 2)];
        }
#pragma unroll
        for (int it = 0; it < 2; ++it) {
            int idx = tid + (it << 8);
            int oo = idx >> 5, kc = idx & 31;
            Ws[kc * 20 + oo] = cw[(size_t)(o0 + oo) * 4096u + k0 + kc];
        }
        __syncthreads();
#pragma unroll
        for (int kc = 0; kc < 32; ++kc) {
            float a0 = As[kc*129+mb], a1 = As[kc*129+mb+1];
            float a2 = As[kc*129+mb+2], a3 = As[kc*129+mb+3];
            float w0 = Ws[kc*20+og], w1 = Ws[kc*20+og+1];
            acc[0][0]+=a0*w0; acc[0][1]+=a0*w1; acc[1][0]+=a1*w0; acc[1][1]+=a1*w1;
            acc[2][0]+=a2*w0; acc[2][1]+=a2*w1; acc[3][0]+=a3*w0; acc[3][1]+=a3*w1;
        }
    }
#pragma unroll
    for (int r = 0; r < 4; ++r)
#pragma unroll
        for (int c = 0; c < 2; ++c) {
            int m = mb + r, o = o0 + og + c;
            comp[(size_t)m * 1024u + o] = acc[r][c] + cb[o];
        }
}

// ============ 3) sliding-window attention v4: natural-layout TC ============
// Qs[64][132], Ks[64][132] (natural [token][d]), Ss[64][68], Al[64]
__global__ void __launch_bounds__(256) win_attn(
        const float* __restrict__ x, float* __restrict__ L, int parity) {
    extern __shared__ float sm[];
    float* Qs = sm;              // 8448
    float* Ks = sm + 8448;       // 8448
    float* Ss = sm + 16896;      // 4352
    float* Al = sm + 21248;      // 64
    const int tid = threadIdx.x;
    const int lane = tid & 31, wid = tid >> 5;
    const int g = lane >> 2, tq = lane & 3;
    const int qt = blockIdx.x;
    const int n = (blockIdx.y << 1) + parity;
    const int b = blockIdx.z >> 3, h = blockIdx.z & 7;
    const int base = n << 8, q0 = base + (qt << 6);
    const float* xb = x + (size_t)b * 4194304u + (h << 7);

#pragma unroll
    for (int it = 0; it < 8; ++it) {
        int i = tid + (it << 8);
        int r = i >> 5, c4 = (i & 31) << 2;
        float4 v = *(const float4*)(xb + (size_t)(q0 + r) * 1024u + c4);
        float* q = &Qs[r * 132 + c4];
        q[0] = f2tff(v.x); q[1] = f2tff(v.y); q[2] = f2tff(v.z); q[3] = f2tff(v.w);
    }

    const int wm = wid >> 1, wn = wid & 1;
    const int m0 = wm << 4;
    const int sn0 = wn << 5;
    const int on0 = wn << 6;
    const int srow = tid >> 2, seg = tid & 3;
    const float scale = 0.08838834764831845f;

    float oacc[8][4];
#pragma unroll
    for (int nt = 0; nt < 8; ++nt)
#pragma unroll
        for (int e = 0; e < 4; ++e) oacc[nt][e] = 0.f;
    float m_i = -1e30f, l_i = 0.f;

    for (int kt = 0; kt < 8; ++kt) {
        __syncthreads();
        const int ktok = base + (kt << 6);
        // coalesced K-tile load, natural layout
#pragma unroll
        for (int it = 0; it < 8; ++it) {
            int i = tid + (it << 8);
            int r = i >> 5, c4 = (i & 31) << 2;
            float4 v = *(const float4*)(xb + (size_t)(ktok + r) * 1024u + c4);
            float* k = &Ks[r * 132 + c4];
            k[0] = f2tff(v.x); k[1] = f2tff(v.y); k[2] = f2tff(v.z); k[3] = f2tff(v.w);
        }
        __syncthreads();

        // ---- scores: S(64x64) = Q @ K^T (B from natural Ks, conflict-free) ----
        float sacc[4][4];
#pragma unroll
        for (int nt = 0; nt < 4; ++nt)
#pragma unroll
            for (int e = 0; e < 4; ++e) sacc[nt][e] = 0.f;
#pragma unroll
        for (int kd = 0; kd < 128; kd += 8) {
            uint32_t a[4];
            a[0] = __float_as_uint(Qs[(m0 + g) * 132 + kd + tq]);
            a[1] = __float_as_uint(Qs[(m0 + g + 8) * 132 + kd + tq]);
            a[2] = __float_as_uint(Qs[(m0 + g) * 132 + kd + tq + 4]);
            a[3] = __float_as_uint(Qs[(m0 + g + 8) * 132 + kd + tq + 4]);
#pragma unroll
            for (int nt = 0; nt < 4; ++nt) {
                int tcol = sn0 + (nt << 3) + g;
                uint32_t bb[2];
                bb[0] = __float_as_uint(Ks[tcol * 132 + kd + tq]);
                bb[1] = __float_as_uint(Ks[tcol * 132 + kd + tq + 4]);
                mma8(sacc[nt], a, bb);
            }
        }
#pragma unroll
        for (int nt = 0; nt < 4; ++nt) {
            int nc = sn0 + (nt << 3) + (tq << 1);
            *(float2*)&Ss[(m0 + g) * 68 + nc] =
                make_float2(sacc[nt][0] * scale, sacc[nt][1] * scale);
            *(float2*)&Ss[(m0 + g + 8) * 68 + nc] =
                make_float2(sacc[nt][2] * scale, sacc[nt][3] * scale);
        }
        __syncthreads();

        // ---- online softmax; exp once; store P tf32 ----
        {
            float* sr = &Ss[srow * 68 + (seg << 4)];
            float mt = -1e30f;
#pragma unroll
            for (int jj = 0; jj < 16; ++jj) mt = fmaxf(mt, sr[jj]);
            mt = fmaxf(mt, __shfl_xor_sync(0xffffffffu, mt, 1));
            mt = fmaxf(mt, __shfl_xor_sync(0xffffffffu, mt, 2));
            float m_new = fmaxf(m_i, mt);
            float alpha = __expf(m_i - m_new);
            float ls = 0.f;
#pragma unroll
            for (int jj = 0; jj < 16; ++jj) {
                float p = __expf(sr[jj] - m_new);
                ls += p;
                sr[jj] = f2tff(p);
            }
            ls += __shfl_xor_sync(0xffffffffu, ls, 1);
            ls += __shfl_xor_sync(0xffffffffu, ls, 2);
            l_i = l_i * alpha + ls;
            m_i = m_new;
            if (seg == 0) Al[srow] = alpha;
        }
        __syncthreads();

        // ---- AV: O(64x128) += P @ V (B from natural Ks, k = token) ----
        float aLo = Al[m0 + g], aHi = Al[m0 + g + 8];
#pragma unroll
        for (int nt = 0; nt < 8; ++nt) {
            oacc[nt][0] *= aLo; oacc[nt][1] *= aLo;
            oacc[nt][2] *= aHi; oacc[nt][3] *= aHi;
        }
#pragma unroll
        for (int kd = 0; kd < 64; kd += 8) {
            uint32_t a[4];
            a[0] = __float_as_uint(Ss[(m0 + g) * 68 + kd + tq]);
            a[1] = __float_as_uint(Ss[(m0 + g + 8) * 68 + kd + tq]);
            a[2] = __float_as_uint(Ss[(m0 + g) * 68 + kd + tq + 4]);
            a[3] = __float_as_uint(Ss[(m0 + g + 8) * 68 + kd + tq + 4]);
#pragma unroll
            for (int nt = 0; nt < 8; ++nt) {
                int dcol = on0 + (nt << 3) + g;
                uint32_t bb[2];
                bb[0] = __float_as_uint(Ks[(kd + tq) * 132 + dcol]);
                bb[1] = __float_as_uint(Ks[(kd + tq + 4) * 132 + dcol]);
                mma8(oacc[nt], a, bb);
            }
        }
    }
    __syncthreads();
    if (seg == 0) Al[srow] = 1.0f / l_i;
    __syncthreads();

    const float twLo = (0.5f + (float)((qt << 6) + m0 + g) * (1.0f / 511.0f)) * Al[m0 + g];
    const float twHi = (0.5f + (float)((qt << 6) + m0 + g + 8) * (1.0f / 511.0f)) * Al[m0 + g + 8];
    float* dLo = L + ((size_t)b * 4096u + q0 + m0 + g) * 1024u + (h << 7);
    float* dHi = dLo + (size_t)8 * 1024u;
#pragma unroll
    for (int nt = 0; nt < 8; ++nt) {
        int dc = on0 + (nt << 3) + (tq << 1);
        if (parity == 0) {
            *(float2*)(dLo + dc) = make_float2(oacc[nt][0] * twLo, oacc[nt][1] * twLo);
            *(float2*)(dHi + dc) = make_float2(oacc[nt][2] * twHi, oacc[nt][3] * twHi);
        } else {
            float2 o = *(float2*)(dLo + dc);
            o.x += oacc[nt][0] * twLo; o.y += oacc[nt][1] * twLo;
            *(float2*)(dLo + dc) = o;
            float2 p = *(float2*)(dHi + dc);
            p.x += oacc[nt][2] * twHi; p.y += oacc[nt][3] * twHi;
            *(float2*)(dHi + dc) = p;
        }
    }
}

// ============ 4) compressed-global attention v2: tensor cores ============
// KVs[128][132] natural, Qs[32][132], Ps[32][132]; 32 queries per block
__global__ void __launch_bounds__(256) gattn(
        const float* __restrict__ x, const float* __restrict__ gmem,
        const float* __restrict__ comp, float* __restrict__ G) {
    extern __shared__ float sm[];
    float* KVs = sm;             // 16896
    float* Qs  = sm + 16896;     // 4224
    float* Ps  = sm + 21120;     // 4224
    const int tid = threadIdx.x;
    const int lane = tid & 31, wid = tid >> 5;
    const int g = lane >> 2, tq = lane & 3;
    const int s0 = blockIdx.x << 5, h = blockIdx.y, b = blockIdx.z;

#pragma unroll
    for (int it = 0; it < 16; ++it) {
        int i = tid + (it << 8);
        int r = i >> 5, c4 = (i & 31) << 2;
        float4 v;
        if (r < 64) v = *(const float4*)(comp + (size_t)((b << 6) + r) * 1024u + (h << 7) + c4);
        else        v = *(const float4*)(gmem + (size_t)((h << 6) + (r - 64)) * 128u + c4);
        float* kv = &KVs[r * 132 + c4];
        kv[0] = f2tff(v.x); kv[1] = f2tff(v.y); kv[2] = f2tff(v.z); kv[3] = f2tff(v.w);
    }
#pragma unroll
    for (int it = 0; it < 4; ++it) {
        int i = tid + (it << 8);
        int r = i >> 5, c4 = (i & 31) << 2;
        float4 v = *(const float4*)(x + (size_t)b * 4194304u + (size_t)(s0 + r) * 1024u + (h << 7) + c4);
        float* q = &Qs[r * 132 + c4];
        q[0] = f2tff(v.x); q[1] = f2tff(v.y); q[2] = f2tff(v.z); q[3] = f2tff(v.w);
    }
    __syncthreads();

    const int wm = wid & 1, wn = wid >> 1;
    const int m0 = wm << 4;
    const int tn0 = wn << 5;
    const float scale = 0.08838834764831845f;

    // scores S[32][128] = Q @ KV^T
    {
        float sacc[4][4];
#pragma unroll
        for (int nt = 0; nt < 4; ++nt)
#pragma unroll
            for (int e = 0; e < 4; ++e) sacc[nt][e] = 0.f;
#pragma unroll
        for (int kd = 0; kd < 128; kd += 8) {
            uint32_t a[4];
            a[0] = __float_as_uint(Qs[(m0 + g) * 132 + kd + tq]);
            a[1] = __float_as_uint(Qs[(m0 + g + 8) * 132 + kd + tq]);
            a[2] = __float_as_uint(Qs[(m0 + g) * 132 + kd + tq + 4]);
            a[3] = __float_as_uint(Qs[(m0 + g + 8) * 132 + kd + tq + 4]);
#pragma unroll
            for (int nt = 0; nt < 4; ++nt) {
                int tcol = tn0 + (nt << 3) + g;
                uint32_t bb[2];
                bb[0] = __float_as_uint(KVs[tcol * 132 + kd + tq]);
                bb[1] = __float_as_uint(KVs[tcol * 132 + kd + tq + 4]);
                mma8(sacc[nt], a, bb);
            }
        }
#pragma unroll
        for (int nt = 0; nt < 4; ++nt) {
            int nc = tn0 + (nt << 3) + (tq << 1);
            *(float2*)&Ps[(m0 + g) * 132 + nc] =
                make_float2(sacc[nt][0] * scale, sacc[nt][1] * scale);
            *(float2*)&Ps[(m0 + g + 8) * 132 + nc] =
                make_float2(sacc[nt][2] * scale, sacc[nt][3] * scale);
        }
    }
    __syncthreads();

    // single-pass softmax over 128 cols (8 threads per row)
    {
        int row = tid >> 3, seg8 = tid & 7;
        float* pr = &Ps[row * 132 + (seg8 << 4)];
        float mt = -1e30f;
        float pv[16];
#pragma unroll
        for (int jj = 0; jj < 16; ++jj) mt = fmaxf(mt, pr[jj]);
        mt = fmaxf(mt, __shfl_xor_sync(0xffffffffu, mt, 1));
        mt = fmaxf(mt, __shfl_xor_sync(0xffffffffu, mt, 2));
        mt = fmaxf(mt, __shfl_xor_sync(0xffffffffu, mt, 4));
        float ssum = 0.f;
#pragma unroll
        for (int jj = 0; jj < 16; ++jj) { pv[jj] = __expf(pr[jj] - mt); ssum += pv[jj]; }
        ssum += __shfl_xor_sync(0xffffffffu, ssum, 1);
        ssum += __shfl_xor_sync(0xffffffffu, ssum, 2);
        ssum += __shfl_xor_sync(0xffffffffu, ssum, 4);
        float invs = 1.0f / ssum;
#pragma unroll
        for (int jj = 0; jj < 16; ++jj) pr[jj] = f2tff(pv[jj] * invs);
    }
    __syncthreads();

    // O[32][128] = P @ KV
    {
        float oacc[4][4];
#pragma unroll
        for (int nt = 0; nt < 4; ++nt)
#pragma unroll
            for (int e = 0; e < 4; ++e) oacc[nt][e] = 0.f;
#pragma unroll
        for (int kd = 0; kd < 128; kd += 8) {
            uint32_t a[4];
            a[0] = __float_as_uint(Ps[(m0 + g) * 132 + kd + tq]);
            a[1] = __float_as_uint(Ps[(m0 + g + 8) * 132 + kd + tq]);
            a[2] = __float_as_uint(Ps[(m0 + g) * 132 + kd + tq + 4]);
            a[3] = __float_as_uint(Ps[(m0 + g + 8) * 132 + kd + tq + 4]);
#pragma unroll
            for (int nt = 0; nt < 4; ++nt) {
                int dcol = tn0 + (nt << 3) + g;
                uint32_t bb[2];
                bb[0] = __float_as_uint(KVs[(kd + tq) * 132 + dcol]);
                bb[1] = __float_as_uint(KVs[(kd + tq + 4) * 132 + dcol]);
                mma8(oacc[nt], a, bb);
            }
        }
        float* gLo = G + ((size_t)b * 4096u + s0 + m0 + g) * 1024u + (h << 7);
        float* gHi = gLo + (size_t)8 * 1024u;
#pragma unroll
        for (int nt = 0; nt < 4; ++nt) {
            int nc = tn0 + (nt << 3) + (tq << 1);
            *(float2*)(gLo + nc) = make_float2(oacc[nt][0], oacc[nt][1]);
            *(float2*)(gHi + nc) = make_float2(oacc[nt][2], oacc[nt][3]);
        }
    }
}

// ============ 5+6) tensor-core tf32 GEMM (invden folded for mode 1) ============
__global__ void __launch_bounds__(256) gemm_tc(
        int mode, const float* __restrict__ A0, const float* __restrict__ A1,
        const float* __restrict__ BCp, const float* __restrict__ W,
        const float* __restrict__ bias, float* __restrict__ C, int K) {
    __shared__ uint32_t As[128 * 36];
    __shared__ uint32_t Bs[32 * 136];
    const int tid = threadIdx.x;
    const int m0 = blockIdx.x << 7, n0 = blockIdx.y << 7;
    const int wid = tid >> 5, lane = tid & 31;
    const int quad = lane >> 2, tq = lane & 3;
    const int wm = wid >> 2, wn = wid & 3;
    const int am = tid >> 1, ak = (tid & 1) << 4;
    const int bk = tid >> 3, bn = (tid & 7) << 4;
    const float sA = (mode == 1) ? invden((m0 + am) & 4095) : 1.0f;

    float acc[4][4][4];
#pragma unroll
    for (int i = 0; i < 4; ++i)
#pragma unroll
        for (int j = 0; j < 4; ++j)
#pragma unroll
            for (int e = 0; e < 4; ++e) acc[i][j][e] = 0.f;

    float4 pa[4], pb[4];
    auto fetch = [&](int kt) {
        bool isL = (mode == 1 && kt < 1024);
        const float* asrc = (mode == 1 && kt >= 1024)
            ? (A1 + (size_t)(m0 + am) * 1024u + (kt - 1024) + ak)
            : (A0 + (size_t)(m0 + am) * 1024u + kt + ak);
#pragma unroll
        for (int q = 0; q < 4; ++q) {
            pa[q] = *(const float4*)(asrc + (q << 2));
            if (isL) { pa[q].x *= sA; pa[q].y *= sA; pa[q].z *= sA; pa[q].w *= sA; }
        }
        const float* bsrc = W + (size_t)(kt + bk) * 1024u + n0 + bn;
#pragma unroll
        for (int q = 0; q < 4; ++q) pb[q] = *(const float4*)(bsrc + (q << 2));
    };
    fetch(0);
    for (int kt = 0; kt < K; kt += 32) {
#pragma unroll
        for (int q = 0; q < 4; ++q) {
            uint32_t* d = &As[am * 36 + ak + (q << 2)];
            d[0] = f2tf(pa[q].x); d[1] = f2tf(pa[q].y); d[2] = f2tf(pa[q].z); d[3] = f2tf(pa[q].w);
            uint32_t* e = &Bs[bk * 136 + bn + (q << 2)];
            e[0] = f2tf(pb[q].x); e[1] = f2tf(pb[q].y); e[2] = f2tf(pb[q].z); e[3] = f2tf(pb[q].w);
        }
        __syncthreads();
        if (kt + 32 < K) fetch(kt + 32);
#pragma unroll
        for (int ks = 0; ks < 4; ++ks) {
            const int k0 = ks << 3;
            uint32_t af[4][4], bf[4][2];
#pragma unroll
            for (int i = 0; i < 4; ++i) {
                int r = (wm << 6) + (i << 4) + quad;
                af[i][0] = As[r * 36 + k0 + tq];
                af[i][1] = As[(r + 8) * 36 + k0 + tq];
                af[i][2] = As[r * 36 + k0 + tq + 4];
                af[i][3] = As[(r + 8) * 36 + k0 + tq + 4];
            }
#pragma unroll
            for (int j = 0; j < 4; ++j) {
                int cidx = (wn << 5) + (j << 3) + quad;
                bf[j][0] = Bs[(k0 + tq) * 136 + cidx];
                bf[j][1] = Bs[(k0 + tq + 4) * 136 + cidx];
            }
#pragma unroll
            for (int i = 0; i < 4; ++i)
#pragma unroll
                for (int j = 0; j < 4; ++j) mma8(acc[i][j], af[i], bf[j]);
        }
        __syncthreads();
    }
#pragma unroll
    for (int i = 0; i < 4; ++i)
#pragma unroll
        for (int j = 0; j < 4; ++j) {
            int mr = m0 + (wm << 6) + (i << 4) + quad;
            int nc = n0 + (wn << 5) + (j << 3) + (tq << 1);
#pragma unroll
            for (int hf = 0; hf < 2; ++hf) {
                int m = mr + (hf << 3);
                size_t bix = (size_t)m * 1024u + nc;
                float invm = (mode == 1) ? invden(m & 4095) : 1.0f;
#pragma unroll
                for (int e = 0; e < 2; ++e) {
                    float z = acc[i][j][(hf << 1) + e] + bias[nc + e];
                    if (mode == 1) {
                        float gg = 1.0f / (1.0f + __expf(-z));
                        C[bix + e] = gg * (A0[bix + e] * invm) + (1.0f - gg) * A1[bix + e] + BCp[bix + e];
                    } else {
                        C[bix + e] = z;
                    }
                }
            }
        }
}

// =====================================================================
extern "C" void kernel_launch(void* const* d_in, const int* in_sizes, int n_in,
                              void* d_out, int out_size) {
    const float* x    = (const float*)d_in[0];
    const float* gmem = (const float*)d_in[1];
    const float* cw   = (const float*)d_in[2];
    const float* cb   = (const float*)d_in[3];
    const float* mw   = (const float*)d_in[4];
    const float* mb   = (const float*)d_in[5];
    const float* ow   = (const float*)d_in[6];
    const float* ob   = (const float*)d_in[7];
    float* out = (float*)d_out;

    float *pL, *pG, *pBC, *pM, *pCOMP;
    cudaGetSymbolAddress((void**)&pL,    g_L);
    cudaGetSymbolAddress((void**)&pG,    g_G);
    cudaGetSymbolAddress((void**)&pBC,   g_BC);
    cudaGetSymbolAddress((void**)&pM,    g_M);
    cudaGetSymbolAddress((void**)&pCOMP, g_COMP);

    const int BC_SMEM = 2 * 16384 * 4;     // 128 KB
    const int WA_SMEM = 21312 * 4;         // 85248 B
    const int GA_SMEM = 25344 * 4;         // 101376 B
    cudaFuncSetAttribute(bc_kernel, cudaFuncAttributeMaxDynamicSharedMemorySize, BC_SMEM);
    cudaFuncSetAttribute(win_attn,  cudaFuncAttributeMaxDynamicSharedMemorySize, WA_SMEM);
    cudaFuncSetAttribute(gattn,     cudaFuncAttributeMaxDynamicSharedMemorySize, GA_SMEM);

    bc_kernel  <<<dim3(256, 2), 512, BC_SMEM>>>(x, pBC);
    conv_kernel<<<64, 256>>>(x, cw, cb, pCOMP);
    win_attn   <<<dim3(8, 8, 16), 256, WA_SMEM>>>(x, pL, 0);
    win_attn   <<<dim3(8, 7, 16), 256, WA_SMEM>>>(x, pL, 1);
    gattn      <<<dim3(128, 8, 2), 256, GA_SMEM>>>(x, gmem, pCOMP, pG);
    gemm_tc    <<<dim3(64, 8), 256>>>(1, pL, pG, pBC, mw, mb, pM, 2048);
    gemm_tc    <<<dim3(64, 8), 256>>>(0, pM, pM, pBC, ow, ob, out, 1024);
}

// round 6
// speedup vs baseline: 3.7119x; 1.0550x over previous
#include <cuda_runtime.h>
#include <math.h>
#include <stdint.h>

__device__ float g_L [2u*4096u*1024u];
__device__ float g_G [2u*4096u*1024u];
__device__ float g_BC[2u*4096u*1024u];
__device__ float g_M [2u*4096u*1024u];
__device__ float g_COMP[2u*64u*1024u];

__device__ __forceinline__ uint32_t f2tf(float x) {
    uint32_t u; asm("cvt.rn.tf32.f32 %0, %1;" : "=r"(u) : "f"(x)); return u;
}
__device__ __forceinline__ float f2tff(float x) {
    uint32_t u; asm("cvt.rn.tf32.f32 %0, %1;" : "=r"(u) : "f"(x));
    return __uint_as_float(u);
}
__device__ __forceinline__ void mma8(float* c, const uint32_t* a, const uint32_t* b) {
    asm volatile("mma.sync.aligned.m16n8k8.row.col.f32.tf32.tf32.f32 "
        "{%0,%1,%2,%3}, {%4,%5,%6,%7}, {%8,%9}, {%0,%1,%2,%3};"
        : "+f"(c[0]), "+f"(c[1]), "+f"(c[2]), "+f"(c[3])
        : "r"(a[0]), "r"(a[1]), "r"(a[2]), "r"(a[3]), "r"(b[0]), "r"(b[1]));
}
__device__ __forceinline__ uint32_t smem_u32(const void* p) {
    uint32_t a;
    asm("{ .reg .u64 t; cvta.to.shared.u64 t, %1; cvt.u32.u64 %0, t; }" : "=r"(a) : "l"(p));
    return a;
}
#define CP16(dst, src) asm volatile("cp.async.cg.shared.global [%0], [%1], 16;" :: "r"(dst), "l"(src))
#define CPCOMMIT()     asm volatile("cp.async.commit_group;" ::: "memory")
#define CPWAIT1()      asm volatile("cp.async.wait_group 1;" ::: "memory")

__device__ __forceinline__ float invden(int s) {
    int n1 = s >> 8, i1 = s & 255;
    float d = 0.f;
    if (n1 <= 14) d += 0.5f + (float)i1 * (1.0f / 511.0f);
    if (n1 >= 1)  d += 0.5f + (float)(i1 + 256) * (1.0f / 511.0f);
    return 1.0f / d;
}

// ============ 1) broadcast diffusion ============
__global__ void bc_kernel(const float* __restrict__ x, float* __restrict__ bc) {
    extern __shared__ float sm[];
    float* bufA = sm; float* bufB = sm + 16384;
    const int tid = threadIdx.x, b = blockIdx.y, d0 = blockIdx.x << 2;
    const float* src = x + (size_t)b * 4194304u + d0;
    for (int s = tid; s < 4096; s += 512)
        *(float4*)&bufA[s << 2] = *(const float4*)(src + (size_t)s * 1024u);
    __syncthreads();
    float acc[32];
#pragma unroll
    for (int e = 0; e < 32; ++e) acc[e] = 0.f;
    float* cur = bufA; float* nxt = bufB;
    for (int st = 1; st < 4096; st <<= 1) {
#pragma unroll
        for (int q = 0; q < 8; ++q) {
            int s = tid + (q << 9), sc = s << 2;
            int sm1 = ((s - st) & 4095) << 2, sp1 = ((s + st) & 4095) << 2;
#pragma unroll
            for (int j = 0; j < 4; ++j) {
                float v = cur[sc + j] + 0.5f * (cur[sm1 + j] + cur[sp1 + j]);
                nxt[sc + j] = v;
                acc[(q << 2) + j] += v;
            }
        }
        __syncthreads();
        float* t = cur; cur = nxt; nxt = t;
    }
    const float inv = 1.0f / 13.0f;
    float* dst = bc + (size_t)b * 4194304u + d0;
#pragma unroll
    for (int q = 0; q < 8; ++q) {
        int s = tid + (q << 9);
        *(float4*)(dst + (size_t)s * 1024u) =
            make_float4(acc[q*4]*inv, acc[q*4+1]*inv, acc[q*4+2]*inv, acc[q*4+3]*inv);
    }
}

// ============ 2) conv1d(k=4,s=4), first 64 tokens ============
__global__ void __launch_bounds__(256) conv_kernel(
        const float* __restrict__ x, const float* __restrict__ cw,
        const float* __restrict__ cb, float* __restrict__ comp) {
    __shared__ float As[32 * 129];
    __shared__ float Ws[32 * 20];
    const int tid = threadIdx.x, o0 = blockIdx.x << 4;
    const int mb = (tid & 31) << 2, og = (tid >> 5) << 1;
    float acc[4][2];
#pragma unroll
    for (int r = 0; r < 4; ++r) { acc[r][0] = 0.f; acc[r][1] = 0.f; }
    for (int k0 = 0; k0 < 4096; k0 += 32) {
        __syncthreads();
#pragma unroll
        for (int it = 0; it < 16; ++it) {
            int idx = tid + (it << 8);
            int m = idx & 127, kc = idx >> 7, k = k0 + kc;
            int bb = m >> 6, t = m & 63;
            As[kc * 129 + m] =
                x[(size_t)bb * 4194304u + (size_t)((t << 2) + (k & 3)) * 1024u + (k >> 2)];
        }
#pragma unroll
        for (int it = 0; it < 2; ++it) {
            int idx = tid + (it << 8);
            int oo = idx >> 5, kc = idx & 31;
            Ws[kc * 20 + oo] = cw[(size_t)(o0 + oo) * 4096u + k0 + kc];
        }
        __syncthreads();
#pragma unroll
        for (int kc = 0; kc < 32; ++kc) {
            float a0 = As[kc*129+mb], a1 = As[kc*129+mb+1];
            float a2 = As[kc*129+mb+2], a3 = As[kc*129+mb+3];
            float w0 = Ws[kc*20+og], w1 = Ws[kc*20+og+1];
            acc[0][0]+=a0*w0; acc[0][1]+=a0*w1; acc[1][0]+=a1*w0; acc[1][1]+=a1*w1;
            acc[2][0]+=a2*w0; acc[2][1]+=a2*w1; acc[3][0]+=a3*w0; acc[3][1]+=a3*w1;
        }
    }
#pragma unroll
    for (int r = 0; r < 4; ++r)
#pragma unroll
        for (int c = 0; c < 2; ++c) {
            int m = mb + r, o = o0 + og + c;
            comp[(size_t)m * 1024u + o] = acc[r][c] + cb[o];
        }
}

// ============ 3) sliding-window attention (TC, fused normalization) ============
__global__ void __launch_bounds__(256) win_attn(
        const float* __restrict__ x, float* __restrict__ L, int parity) {
    extern __shared__ float sm[];
    float* Qs = sm;              // 8448
    float* Ks = sm + 8448;       // 8448
    float* Ss = sm + 16896;      // 4352
    float* Al = sm + 21248;      // 64
    const int tid = threadIdx.x;
    const int lane = tid & 31, wid = tid >> 5;
    const int g = lane >> 2, tq = lane & 3;
    const int qt = blockIdx.x;
    const int n = (blockIdx.y << 1) + parity;
    const int b = blockIdx.z >> 3, h = blockIdx.z & 7;
    const int base = n << 8, q0 = base + (qt << 6);
    const float* xb = x + (size_t)b * 4194304u + (h << 7);

#pragma unroll
    for (int it = 0; it < 8; ++it) {
        int i = tid + (it << 8);
        int r = i >> 5, c4 = (i & 31) << 2;
        float4 v = *(const float4*)(xb + (size_t)(q0 + r) * 1024u + c4);
        float* q = &Qs[r * 132 + c4];
        q[0] = f2tff(v.x); q[1] = f2tff(v.y); q[2] = f2tff(v.z); q[3] = f2tff(v.w);
    }

    const int wm = wid >> 1, wn = wid & 1;
    const int m0 = wm << 4;
    const int sn0 = wn << 5;
    const int on0 = wn << 6;
    const int srow = tid >> 2, seg = tid & 3;
    const float scale = 0.08838834764831845f;

    float oacc[8][4];
#pragma unroll
    for (int nt = 0; nt < 8; ++nt)
#pragma unroll
        for (int e = 0; e < 4; ++e) oacc[nt][e] = 0.f;
    float m_i = -1e30f, l_i = 0.f;

    for (int kt = 0; kt < 8; ++kt) {
        __syncthreads();
        const int ktok = base + (kt << 6);
#pragma unroll
        for (int it = 0; it < 8; ++it) {
            int i = tid + (it << 8);
            int r = i >> 5, c4 = (i & 31) << 2;
            float4 v = *(const float4*)(xb + (size_t)(ktok + r) * 1024u + c4);
            float* k = &Ks[r * 132 + c4];
            k[0] = f2tff(v.x); k[1] = f2tff(v.y); k[2] = f2tff(v.z); k[3] = f2tff(v.w);
        }
        __syncthreads();

        float sacc[4][4];
#pragma unroll
        for (int nt = 0; nt < 4; ++nt)
#pragma unroll
            for (int e = 0; e < 4; ++e) sacc[nt][e] = 0.f;
#pragma unroll
        for (int kd = 0; kd < 128; kd += 8) {
            uint32_t a[4];
            a[0] = __float_as_uint(Qs[(m0 + g) * 132 + kd + tq]);
            a[1] = __float_as_uint(Qs[(m0 + g + 8) * 132 + kd + tq]);
            a[2] = __float_as_uint(Qs[(m0 + g) * 132 + kd + tq + 4]);
            a[3] = __float_as_uint(Qs[(m0 + g + 8) * 132 + kd + tq + 4]);
#pragma unroll
            for (int nt = 0; nt < 4; ++nt) {
                int tcol = sn0 + (nt << 3) + g;
                uint32_t bb[2];
                bb[0] = __float_as_uint(Ks[tcol * 132 + kd + tq]);
                bb[1] = __float_as_uint(Ks[tcol * 132 + kd + tq + 4]);
                mma8(sacc[nt], a, bb);
            }
        }
#pragma unroll
        for (int nt = 0; nt < 4; ++nt) {
            int nc = sn0 + (nt << 3) + (tq << 1);
            *(float2*)&Ss[(m0 + g) * 68 + nc] =
                make_float2(sacc[nt][0] * scale, sacc[nt][1] * scale);
            *(float2*)&Ss[(m0 + g + 8) * 68 + nc] =
                make_float2(sacc[nt][2] * scale, sacc[nt][3] * scale);
        }
        __syncthreads();

        {
            float* sr = &Ss[srow * 68 + (seg << 4)];
            float mt = -1e30f;
#pragma unroll
            for (int jj = 0; jj < 16; ++jj) mt = fmaxf(mt, sr[jj]);
            mt = fmaxf(mt, __shfl_xor_sync(0xffffffffu, mt, 1));
            mt = fmaxf(mt, __shfl_xor_sync(0xffffffffu, mt, 2));
            float m_new = fmaxf(m_i, mt);
            float alpha = __expf(m_i - m_new);
            float ls = 0.f;
#pragma unroll
            for (int jj = 0; jj < 16; ++jj) {
                float p = __expf(sr[jj] - m_new);
                ls += p;
                sr[jj] = f2tff(p);
            }
            ls += __shfl_xor_sync(0xffffffffu, ls, 1);
            ls += __shfl_xor_sync(0xffffffffu, ls, 2);
            l_i = l_i * alpha + ls;
            m_i = m_new;
            if (seg == 0) Al[srow] = alpha;
        }
        __syncthreads();

        float aLo = Al[m0 + g], aHi = Al[m0 + g + 8];
#pragma unroll
        for (int nt = 0; nt < 8; ++nt) {
            oacc[nt][0] *= aLo; oacc[nt][1] *= aLo;
            oacc[nt][2] *= aHi; oacc[nt][3] *= aHi;
        }
#pragma unroll
        for (int kd = 0; kd < 64; kd += 8) {
            uint32_t a[4];
            a[0] = __float_as_uint(Ss[(m0 + g) * 68 + kd + tq]);
            a[1] = __float_as_uint(Ss[(m0 + g + 8) * 68 + kd + tq]);
            a[2] = __float_as_uint(Ss[(m0 + g) * 68 + kd + tq + 4]);
            a[3] = __float_as_uint(Ss[(m0 + g + 8) * 68 + kd + tq + 4]);
#pragma unroll
            for (int nt = 0; nt < 8; ++nt) {
                int dcol = on0 + (nt << 3) + g;
                uint32_t bb[2];
                bb[0] = __float_as_uint(Ks[(kd + tq) * 132 + dcol]);
                bb[1] = __float_as_uint(Ks[(kd + tq + 4) * 132 + dcol]);
                mma8(oacc[nt], a, bb);
            }
        }
    }
    __syncthreads();
    if (seg == 0) Al[srow] = 1.0f / l_i;
    __syncthreads();

    // fused overlap-add normalization
    const int iwLo = (qt << 6) + m0 + g;          // index within window (0..511)
    const int iwHi = iwLo + 8;
    const int sLo = base + iwLo, sHi = base + iwHi;  // global token index
    const float triLo = 0.5f + (float)iwLo * (1.0f / 511.0f);
    const float triHi = 0.5f + (float)iwHi * (1.0f / 511.0f);
    float* dLo = L + ((size_t)b * 4096u + sLo) * 1024u + (h << 7);
    float* dHi = dLo + (size_t)8 * 1024u;
    if (parity == 0) {
        const bool snLo = (sLo < 256) || (sLo >= 3840);
        const bool snHi = (sHi < 256) || (sHi >= 3840);
        const float twLo = (snLo ? 1.0f : triLo) * Al[m0 + g];
        const float twHi = (snHi ? 1.0f : triHi) * Al[m0 + g + 8];
#pragma unroll
        for (int nt = 0; nt < 8; ++nt) {
            int dc = on0 + (nt << 3) + (tq << 1);
            *(float2*)(dLo + dc) = make_float2(oacc[nt][0] * twLo, oacc[nt][1] * twLo);
            *(float2*)(dHi + dc) = make_float2(oacc[nt][2] * twHi, oacc[nt][3] * twHi);
        }
    } else {
        const float twLo = triLo * Al[m0 + g];
        const float twHi = triHi * Al[m0 + g + 8];
        const float ivLo = invden(sLo), ivHi = invden(sHi);
#pragma unroll
        for (int nt = 0; nt < 8; ++nt) {
            int dc = on0 + (nt << 3) + (tq << 1);
            float2 o = *(float2*)(dLo + dc);
            o.x = (o.x + oacc[nt][0] * twLo) * ivLo;
            o.y = (o.y + oacc[nt][1] * twLo) * ivLo;
            *(float2*)(dLo + dc) = o;
            float2 p = *(float2*)(dHi + dc);
            p.x = (p.x + oacc[nt][2] * twHi) * ivHi;
            p.y = (p.y + oacc[nt][3] * twHi) * ivHi;
            *(float2*)(dHi + dc) = p;
        }
    }
}

// ============ 4) compressed-global attention (TC) ============
__global__ void __launch_bounds__(256) gattn(
        const float* __restrict__ x, const float* __restrict__ gmem,
        const float* __restrict__ comp, float* __restrict__ G) {
    extern __shared__ float sm[];
    float* KVs = sm;             // 16896
    float* Qs  = sm + 16896;     // 4224
    float* Ps  = sm + 21120;     // 4224
    const int tid = threadIdx.x;
    const int lane = tid & 31, wid = tid >> 5;
    const int g = lane >> 2, tq = lane & 3;
    const int s0 = blockIdx.x << 5, h = blockIdx.y, b = blockIdx.z;

#pragma unroll
    for (int it = 0; it < 16; ++it) {
        int i = tid + (it << 8);
        int r = i >> 5, c4 = (i & 31) << 2;
        float4 v;
        if (r < 64) v = *(const float4*)(comp + (size_t)((b << 6) + r) * 1024u + (h << 7) + c4);
        else        v = *(const float4*)(gmem + (size_t)((h << 6) + (r - 64)) * 128u + c4);
        float* kv = &KVs[r * 132 + c4];
        kv[0] = f2tff(v.x); kv[1] = f2tff(v.y); kv[2] = f2tff(v.z); kv[3] = f2tff(v.w);
    }
#pragma unroll
    for (int it = 0; it < 4; ++it) {
        int i = tid + (it << 8);
        int r = i >> 5, c4 = (i & 31) << 2;
        float4 v = *(const float4*)(x + (size_t)b * 4194304u + (size_t)(s0 + r) * 1024u + (h << 7) + c4);
        float* q = &Qs[r * 132 + c4];
        q[0] = f2tff(v.x); q[1] = f2tff(v.y); q[2] = f2tff(v.z); q[3] = f2tff(v.w);
    }
    __syncthreads();

    const int wm = wid & 1, wn = wid >> 1;
    const int m0 = wm << 4;
    const int tn0 = wn << 5;
    const float scale = 0.08838834764831845f;

    {
        float sacc[4][4];
#pragma unroll
        for (int nt = 0; nt < 4; ++nt)
#pragma unroll
            for (int e = 0; e < 4; ++e) sacc[nt][e] = 0.f;
#pragma unroll
        for (int kd = 0; kd < 128; kd += 8) {
            uint32_t a[4];
            a[0] = __float_as_uint(Qs[(m0 + g) * 132 + kd + tq]);
            a[1] = __float_as_uint(Qs[(m0 + g + 8) * 132 + kd + tq]);
            a[2] = __float_as_uint(Qs[(m0 + g) * 132 + kd + tq + 4]);
            a[3] = __float_as_uint(Qs[(m0 + g + 8) * 132 + kd + tq + 4]);
#pragma unroll
            for (int nt = 0; nt < 4; ++nt) {
                int tcol = tn0 + (nt << 3) + g;
                uint32_t bb[2];
                bb[0] = __float_as_uint(KVs[tcol * 132 + kd + tq]);
                bb[1] = __float_as_uint(KVs[tcol * 132 + kd + tq + 4]);
                mma8(sacc[nt], a, bb);
            }
        }
#pragma unroll
        for (int nt = 0; nt < 4; ++nt) {
            int nc = tn0 + (nt << 3) + (tq << 1);
            *(float2*)&Ps[(m0 + g) * 132 + nc] =
                make_float2(sacc[nt][0] * scale, sacc[nt][1] * scale);
            *(float2*)&Ps[(m0 + g + 8) * 132 + nc] =
                make_float2(sacc[nt][2] * scale, sacc[nt][3] * scale);
        }
    }
    __syncthreads();

    {
        int row = tid >> 3, seg8 = tid & 7;
        float* pr = &Ps[row * 132 + (seg8 << 4)];
        float mt = -1e30f;
        float pv[16];
#pragma unroll
        for (int jj = 0; jj < 16; ++jj) mt = fmaxf(mt, pr[jj]);
        mt = fmaxf(mt, __shfl_xor_sync(0xffffffffu, mt, 1));
        mt = fmaxf(mt, __shfl_xor_sync(0xffffffffu, mt, 2));
        mt = fmaxf(mt, __shfl_xor_sync(0xffffffffu, mt, 4));
        float ssum = 0.f;
#pragma unroll
        for (int jj = 0; jj < 16; ++jj) { pv[jj] = __expf(pr[jj] - mt); ssum += pv[jj]; }
        ssum += __shfl_xor_sync(0xffffffffu, ssum, 1);
        ssum += __shfl_xor_sync(0xffffffffu, ssum, 2);
        ssum += __shfl_xor_sync(0xffffffffu, ssum, 4);
        float invs = 1.0f / ssum;
#pragma unroll
        for (int jj = 0; jj < 16; ++jj) pr[jj] = f2tff(pv[jj] * invs);
    }
    __syncthreads();

    {
        float oacc[4][4];
#pragma unroll
        for (int nt = 0; nt < 4; ++nt)
#pragma unroll
            for (int e = 0; e < 4; ++e) oacc[nt][e] = 0.f;
#pragma unroll
        for (int kd = 0; kd < 128; kd += 8) {
            uint32_t a[4];
            a[0] = __float_as_uint(Ps[(m0 + g) * 132 + kd + tq]);
            a[1] = __float_as_uint(Ps[(m0 + g + 8) * 132 + kd + tq]);
            a[2] = __float_as_uint(Ps[(m0 + g) * 132 + kd + tq + 4]);
            a[3] = __float_as_uint(Ps[(m0 + g + 8) * 132 + kd + tq + 4]);
#pragma unroll
            for (int nt = 0; nt < 4; ++nt) {
                int dcol = tn0 + (nt << 3) + g;
                uint32_t bb[2];
                bb[0] = __float_as_uint(KVs[(kd + tq) * 132 + dcol]);
                bb[1] = __float_as_uint(KVs[(kd + tq + 4) * 132 + dcol]);
                mma8(oacc[nt], a, bb);
            }
        }
        float* gLo = G + ((size_t)b * 4096u + s0 + m0 + g) * 1024u + (h << 7);
        float* gHi = gLo + (size_t)8 * 1024u;
#pragma unroll
        for (int nt = 0; nt < 4; ++nt) {
            int nc = tn0 + (nt << 3) + (tq << 1);
            *(float2*)(gLo + nc) = make_float2(oacc[nt][0], oacc[nt][1]);
            *(float2*)(gHi + nc) = make_float2(oacc[nt][2], oacc[nt][3]);
        }
    }
}

// ============ 5+6) cp.async-pipelined tf32 GEMM ============
// stage layout: A[128][36] then B[32][136], 8960 floats per stage, 3 stages
__global__ void __launch_bounds__(256) gemm_tc(
        int mode, const float* __restrict__ A0, const float* __restrict__ A1,
        const float* __restrict__ BCp, const float* __restrict__ W,
        const float* __restrict__ bias, float* __restrict__ C, int K) {
    extern __shared__ float gsm[];
    const int tid = threadIdx.x;
    const int m0 = blockIdx.x << 7, n0 = blockIdx.y << 7;
    const int wid = tid >> 5, lane = tid & 31;
    const int quad = lane >> 2, tq = lane & 3;
    const int wm = wid >> 2, wn = wid & 3;
    const int am = tid >> 1, ak = (tid & 1) << 4;
    const int bk = tid >> 3, bn = (tid & 7) << 4;
    const uint32_t sbase = smem_u32(gsm);

    auto issue = [&](int kt, int slot) {
        uint32_t aoff = sbase + (uint32_t)(slot * 8960 + am * 36 + ak) * 4u;
        const float* asrc = (mode == 1 && kt >= 1024)
            ? (A1 + (size_t)(m0 + am) * 1024u + (kt - 1024) + ak)
            : (A0 + (size_t)(m0 + am) * 1024u + kt + ak);
        CP16(aoff, asrc); CP16(aoff + 16, asrc + 4);
        CP16(aoff + 32, asrc + 8); CP16(aoff + 48, asrc + 12);
        uint32_t boff = sbase + (uint32_t)(slot * 8960 + 4608 + bk * 136 + bn) * 4u;
        const float* bsrc = W + (size_t)(kt + bk) * 1024u + n0 + bn;
        CP16(boff, bsrc); CP16(boff + 16, bsrc + 4);
        CP16(boff + 32, bsrc + 8); CP16(boff + 48, bsrc + 12);
        CPCOMMIT();
    };

    float acc[4][4][4];
#pragma unroll
    for (int i = 0; i < 4; ++i)
#pragma unroll
        for (int j = 0; j < 4; ++j)
#pragma unroll
            for (int e = 0; e < 4; ++e) acc[i][j][e] = 0.f;

    issue(0, 0);
    issue(32, 1);

    for (int kt = 0; kt < K; kt += 32) {
        CPWAIT1();
        __syncthreads();
        int nk = kt + 64;
        if (nk < K) issue(nk, ((kt >> 5) + 2) % 3);
        else        CPCOMMIT();

        const float* Asb = gsm + ((kt >> 5) % 3) * 8960;
        const float* Bsb = Asb + 4608;
#pragma unroll
        for (int ks = 0; ks < 4; ++ks) {
            const int k0 = ks << 3;
            uint32_t af[4][4], bf[4][2];
#pragma unroll
            for (int i = 0; i < 4; ++i) {
                int r = (wm << 6) + (i << 4) + quad;
                af[i][0] = __float_as_uint(Asb[r * 36 + k0 + tq]);
                af[i][1] = __float_as_uint(Asb[(r + 8) * 36 + k0 + tq]);
                af[i][2] = __float_as_uint(Asb[r * 36 + k0 + tq + 4]);
                af[i][3] = __float_as_uint(Asb[(r + 8) * 36 + k0 + tq + 4]);
            }
#pragma unroll
            for (int j = 0; j < 4; ++j) {
                int cidx = (wn << 5) + (j << 3) + quad;
                bf[j][0] = __float_as_uint(Bsb[(k0 + tq) * 136 + cidx]);
                bf[j][1] = __float_as_uint(Bsb[(k0 + tq + 4) * 136 + cidx]);
            }
#pragma unroll
            for (int i = 0; i < 4; ++i)
#pragma unroll
                for (int j = 0; j < 4; ++j) mma8(acc[i][j], af[i], bf[j]);
        }
    }

#pragma unroll
    for (int i = 0; i < 4; ++i)
#pragma unroll
        for (int j = 0; j < 4; ++j) {
            int mr = m0 + (wm << 6) + (i << 4) + quad;
            int nc = n0 + (wn << 5) + (j << 3) + (tq << 1);
#pragma unroll
            for (int hf = 0; hf < 2; ++hf) {
                int m = mr + (hf << 3);
                size_t bix = (size_t)m * 1024u + nc;
#pragma unroll
                for (int e = 0; e < 2; ++e) {
                    float z = acc[i][j][(hf << 1) + e] + bias[nc + e];
                    if (mode == 1) {
                        float gg = 1.0f / (1.0f + __expf(-z));
                        C[bix + e] = gg * A0[bix + e] + (1.0f - gg) * A1[bix + e] + BCp[bix + e];
                    } else {
                        C[bix + e] = z;
                    }
                }
            }
        }
}

// =====================================================================
extern "C" void kernel_launch(void* const* d_in, const int* in_sizes, int n_in,
                              void* d_out, int out_size) {
    const float* x    = (const float*)d_in[0];
    const float* gmem = (const float*)d_in[1];
    const float* cw   = (const float*)d_in[2];
    const float* cb   = (const float*)d_in[3];
    const float* mw   = (const float*)d_in[4];
    const float* mb   = (const float*)d_in[5];
    const float* ow   = (const float*)d_in[6];
    const float* ob   = (const float*)d_in[7];
    float* out = (float*)d_out;

    float *pL, *pG, *pBC, *pM, *pCOMP;
    cudaGetSymbolAddress((void**)&pL,    g_L);
    cudaGetSymbolAddress((void**)&pG,    g_G);
    cudaGetSymbolAddress((void**)&pBC,   g_BC);
    cudaGetSymbolAddress((void**)&pM,    g_M);
    cudaGetSymbolAddress((void**)&pCOMP, g_COMP);

    // lazily created once (host-side resources only; never during capture)
    static cudaStream_t s1 = nullptr, s2 = nullptr, s3 = nullptr;
    static cudaEvent_t evR = nullptr, ev1 = nullptr, ev2 = nullptr, ev3 = nullptr;
    if (s1 == nullptr) {
        cudaStreamCreateWithFlags(&s1, cudaStreamNonBlocking);
        cudaStreamCreateWithFlags(&s2, cudaStreamNonBlocking);
        cudaStreamCreateWithFlags(&s3, cudaStreamNonBlocking);
        cudaEventCreateWithFlags(&evR, cudaEventDisableTiming);
        cudaEventCreateWithFlags(&ev1, cudaEventDisableTiming);
        cudaEventCreateWithFlags(&ev2, cudaEventDisableTiming);
        cudaEventCreateWithFlags(&ev3, cudaEventDisableTiming);
    }

    const int BC_SMEM = 2 * 16384 * 4;     // 128 KB
    const int WA_SMEM = 21312 * 4;         // 85248 B
    const int GA_SMEM = 25344 * 4;         // 101376 B
    const int GE_SMEM = 3 * 8960 * 4;      // 107520 B
    cudaFuncSetAttribute(bc_kernel, cudaFuncAttributeMaxDynamicSharedMemorySize, BC_SMEM);
    cudaFuncSetAttribute(win_attn,  cudaFuncAttributeMaxDynamicSharedMemorySize, WA_SMEM);
    cudaFuncSetAttribute(gattn,     cudaFuncAttributeMaxDynamicSharedMemorySize, GA_SMEM);
    cudaFuncSetAttribute(gemm_tc,   cudaFuncAttributeMaxDynamicSharedMemorySize, GE_SMEM);

    // fork: three independent chains off the (captured) legacy stream
    cudaEventRecord(evR, 0);
    cudaStreamWaitEvent(s1, evR, 0);
    cudaStreamWaitEvent(s2, evR, 0);
    cudaStreamWaitEvent(s3, evR, 0);

    bc_kernel  <<<dim3(256, 2), 512, BC_SMEM, s1>>>(x, pBC);
    conv_kernel<<<64, 256, 0, s2>>>(x, cw, cb, pCOMP);
    gattn      <<<dim3(128, 8, 2), 256, GA_SMEM, s2>>>(x, gmem, pCOMP, pG);
    win_attn   <<<dim3(8, 8, 16), 256, WA_SMEM, s3>>>(x, pL, 0);
    win_attn   <<<dim3(8, 7, 16), 256, WA_SMEM, s3>>>(x, pL, 1);

    cudaEventRecord(ev1, s1);
    cudaEventRecord(ev2, s2);
    cudaEventRecord(ev3, s3);
    cudaStreamWaitEvent(0, ev1, 0);
    cudaStreamWaitEvent(0, ev2, 0);
    cudaStreamWaitEvent(0, ev3, 0);

    gemm_tc<<<dim3(64, 8), 256, GE_SMEM>>>(1, pL, pG, pBC, mw, mb, pM, 2048);
    gemm_tc<<<dim3(64, 8), 256, GE_SMEM>>>(0, pM, pM, pBC, ow, ob, out, 1024);
}